// round 1
// baseline (speedup 1.0000x reference)
#include <cuda_runtime.h>
#include <cuda_bf16.h>

// ---------------------------------------------------------------------------
// MoEEncoderLayer: B=2 L=2048 D=512 H=8 E=8 K=2 DF=2048
// Output layout in d_out (float32): [out: T*D][attn: B*H*L*L][aug_loss: 1]
// ---------------------------------------------------------------------------

#define Bb 2
#define Ls 2048
#define Dm 512
#define Hh 8
#define Ee 8
#define KTOP 2
#define Fd 2048
#define Hd 64
#define Tt (Bb*Ls)                      // 4096

static const long long ATTN_OFF = (long long)Tt * Dm;                      // 2097152
static const long long LOSS_OFF = ATTN_OFF + (long long)Bb*Hh*Ls*Ls;       // 69206016

// ------------------------- scratch (device globals) ------------------------
__device__ float g_q[Tt*Dm];
__device__ float g_k[Tt*Dm];
__device__ float g_v[Tt*Dm];
__device__ float g_ctx[Tt*Dm];
__device__ float g_tmp[Tt*Dm];
__device__ float g_x1[Tt*Dm];
__device__ float g_gh[Tt*Dm];
__device__ float g_logits[Tt*Ee];
__device__ float g_wk[Tt*KTOP];
__device__ int   g_cnt[Ee];
__device__ int   g_list[Ee*Tt];
__device__ float g_eh[Tt*KTOP*Fd];      // gathered expert hidden (8192 x 2048)
__device__ float g_y[Tt*KTOP*Dm];       // per-(token,k) expert output (8192 x 512)
__device__ float g_genh[Tt*Fd];         // general-expert hidden
__device__ float g_gen[Tt*Dm];

// ------------------------------- helpers -----------------------------------
__device__ __forceinline__ float gelu_tanh(float x) {
    float x3 = x * x * x;
    float t  = tanhf(0.7978845608028654f * (x + 0.044715f * x3));
    return 0.5f * x * (1.0f + t);
}

__device__ __forceinline__ float warpReduceSum(float v) {
    #pragma unroll
    for (int o = 16; o > 0; o >>= 1) v += __shfl_xor_sync(0xffffffffu, v, o);
    return v;
}
__device__ __forceinline__ float warpReduceMax(float v) {
    #pragma unroll
    for (int o = 16; o > 0; o >>= 1) v = fmaxf(v, __shfl_xor_sync(0xffffffffu, v, o));
    return v;
}

// 256-thread block reductions, result broadcast to all threads
__device__ __forceinline__ float blockReduceSum256(float v) {
    __shared__ float sh[33];
    int tid = threadIdx.x, lane = tid & 31, wid = tid >> 5;
    v = warpReduceSum(v);
    if (lane == 0) sh[wid] = v;
    __syncthreads();
    if (tid < 8) {
        float x = sh[tid];
        #pragma unroll
        for (int o = 4; o > 0; o >>= 1) x += __shfl_xor_sync(0xffu, x, o);
        if (tid == 0) sh[32] = x;
    }
    __syncthreads();
    float r = sh[32];
    __syncthreads();
    return r;
}
__device__ __forceinline__ float blockReduceMax256(float v) {
    __shared__ float sh[33];
    int tid = threadIdx.x, lane = tid & 31, wid = tid >> 5;
    v = warpReduceMax(v);
    if (lane == 0) sh[wid] = v;
    __syncthreads();
    if (tid < 8) {
        float x = sh[tid];
        #pragma unroll
        for (int o = 4; o > 0; o >>= 1) x = fmaxf(x, __shfl_xor_sync(0xffu, x, o));
        if (tid == 0) sh[32] = x;
    }
    __syncthreads();
    float r = sh[32];
    __syncthreads();
    return r;
}

// ------------------- generic tiled GEMM:  C = act(A*W + b) ------------------
// A: [M x Kd] row-major, W: [Kd x N] row-major, grid = (N/64, M/64), 256 thr.
template<int ACT>
__global__ void __launch_bounds__(256)
gemm_bias_kernel(const float* __restrict__ A, const float* __restrict__ W,
                 const float* __restrict__ bias, float* __restrict__ C,
                 int N, int Kd)
{
    __shared__ float As[16][65];
    __shared__ float Bs[16][68];
    const int tid = threadIdx.x, tx = tid & 15, ty = tid >> 4;
    const int m0 = blockIdx.y * 64, n0 = blockIdx.x * 64;
    const int am = tid >> 2, ak = (tid & 3) * 4;
    const int bk = tid >> 4, bn = (tid & 15) * 4;
    const float* Ap = A + (long long)(m0 + am) * Kd + ak;
    const float* Wp = W + (long long)bk * N + n0 + bn;
    float acc[4][4] = {};
    for (int k0 = 0; k0 < Kd; k0 += 16) {
        float4 a4 = *(const float4*)(Ap + k0);
        As[ak+0][am] = a4.x; As[ak+1][am] = a4.y; As[ak+2][am] = a4.z; As[ak+3][am] = a4.w;
        float4 b4 = *(const float4*)(Wp + (long long)k0 * N);
        *(float4*)&Bs[bk][bn] = b4;
        __syncthreads();
        #pragma unroll
        for (int kk = 0; kk < 16; kk++) {
            float a[4], b[4];
            #pragma unroll
            for (int i = 0; i < 4; i++) a[i] = As[kk][ty*4 + i];
            #pragma unroll
            for (int j = 0; j < 4; j++) b[j] = Bs[kk][tx*4 + j];
            #pragma unroll
            for (int i = 0; i < 4; i++)
                #pragma unroll
                for (int j = 0; j < 4; j++) acc[i][j] += a[i] * b[j];
        }
        __syncthreads();
    }
    #pragma unroll
    for (int i = 0; i < 4; i++) {
        int m = m0 + ty*4 + i;
        #pragma unroll
        for (int j = 0; j < 4; j++) {
            int n = n0 + tx*4 + j;
            float v = acc[i][j] + bias[n];
            if (ACT) v = gelu_tanh(v);
            C[(long long)m * N + n] = v;
        }
    }
}

// ---------------- attention: scores = q k^T / sqrt(Hd) ----------------------
// grid = (L/64, L/64, B*H)
__global__ void __launch_bounds__(256)
attn_scores_kernel(const float* __restrict__ q, const float* __restrict__ k,
                   float* __restrict__ attn)
{
    __shared__ float Qs[16][65];
    __shared__ float Ks[16][65];
    const int tid = threadIdx.x, tx = tid & 15, ty = tid >> 4;
    const int bh = blockIdx.z; const int b = bh >> 3, h = bh & 7;
    const int i0 = blockIdx.y * 64, j0 = blockIdx.x * 64;
    const int am = tid >> 2, ak = (tid & 3) * 4;
    const float* Qp = q + (long long)(b*Ls + i0 + am) * Dm + h*Hd + ak;
    const float* Kp = k + (long long)(b*Ls + j0 + am) * Dm + h*Hd + ak;
    float acc[4][4] = {};
    for (int k0 = 0; k0 < Hd; k0 += 16) {
        float4 a4 = *(const float4*)(Qp + k0);
        Qs[ak+0][am] = a4.x; Qs[ak+1][am] = a4.y; Qs[ak+2][am] = a4.z; Qs[ak+3][am] = a4.w;
        float4 b4 = *(const float4*)(Kp + k0);
        Ks[ak+0][am] = b4.x; Ks[ak+1][am] = b4.y; Ks[ak+2][am] = b4.z; Ks[ak+3][am] = b4.w;
        __syncthreads();
        #pragma unroll
        for (int kk = 0; kk < 16; kk++) {
            float a[4], b2[4];
            #pragma unroll
            for (int i = 0; i < 4; i++) a[i] = Qs[kk][ty*4 + i];
            #pragma unroll
            for (int j = 0; j < 4; j++) b2[j] = Ks[kk][tx*4 + j];
            #pragma unroll
            for (int i = 0; i < 4; i++)
                #pragma unroll
                for (int j = 0; j < 4; j++) acc[i][j] += a[i] * b2[j];
        }
        __syncthreads();
    }
    float* O = attn + (long long)bh * Ls * Ls;
    #pragma unroll
    for (int i = 0; i < 4; i++)
        #pragma unroll
        for (int j = 0; j < 4; j++)
            O[(long long)(i0 + ty*4 + i) * Ls + (j0 + tx*4 + j)] = acc[i][j] * 0.125f;
}

// row softmax in-place over attn rows (2048 cols), one block/row, values in regs
__global__ void __launch_bounds__(256)
softmax_kernel(float* __restrict__ attn)
{
    const long long row = blockIdx.x;
    float* p = attn + row * (long long)Ls;
    const int tid = threadIdx.x;
    float v[8];
    float mx = -1e30f;
    #pragma unroll
    for (int i = 0; i < 8; i++) { v[i] = p[tid + i*256]; mx = fmaxf(mx, v[i]); }
    mx = blockReduceMax256(mx);
    float s = 0.f;
    #pragma unroll
    for (int i = 0; i < 8; i++) { v[i] = __expf(v[i] - mx); s += v[i]; }
    s = blockReduceSum256(s);
    float inv = 1.f / s;
    #pragma unroll
    for (int i = 0; i < 8; i++) p[tid + i*256] = v[i] * inv;
}

// ctx = attn @ v   grid = (1, L/64, B*H)
__global__ void __launch_bounds__(256)
attn_v_kernel(const float* __restrict__ attn, const float* __restrict__ v,
              float* __restrict__ ctx)
{
    __shared__ float As[16][65];
    __shared__ float Bs[16][68];
    const int tid = threadIdx.x, tx = tid & 15, ty = tid >> 4;
    const int bh = blockIdx.z; const int b = bh >> 3, h = bh & 7;
    const int i0 = blockIdx.y * 64;
    const int am = tid >> 2, ak = (tid & 3) * 4;
    const int bk = tid >> 4, bn = (tid & 15) * 4;
    const float* Ap = attn + (long long)bh * Ls * Ls + (long long)(i0 + am) * Ls + ak;
    const float* Vp = v + (long long)(b*Ls + bk) * Dm + h*Hd + bn;
    float acc[4][4] = {};
    for (int k0 = 0; k0 < Ls; k0 += 16) {
        float4 a4 = *(const float4*)(Ap + k0);
        As[ak+0][am] = a4.x; As[ak+1][am] = a4.y; As[ak+2][am] = a4.z; As[ak+3][am] = a4.w;
        float4 b4 = *(const float4*)(Vp + (long long)k0 * Dm);
        *(float4*)&Bs[bk][bn] = b4;
        __syncthreads();
        #pragma unroll
        for (int kk = 0; kk < 16; kk++) {
            float a[4], b2[4];
            #pragma unroll
            for (int i = 0; i < 4; i++) a[i] = As[kk][ty*4 + i];
            #pragma unroll
            for (int j = 0; j < 4; j++) b2[j] = Bs[kk][tx*4 + j];
            #pragma unroll
            for (int i = 0; i < 4; i++)
                #pragma unroll
                for (int j = 0; j < 4; j++) acc[i][j] += a[i] * b2[j];
        }
        __syncthreads();
    }
    #pragma unroll
    for (int i = 0; i < 4; i++)
        #pragma unroll
        for (int j = 0; j < 4; j++)
            ctx[(long long)(b*Ls + i0 + ty*4 + i) * Dm + h*Hd + tx*4 + j] = acc[i][j];
}

// out = LayerNorm(a + b), one block per token (256 thr, 2 elems each)
__global__ void __launch_bounds__(256)
add_ln_kernel(const float* __restrict__ a, const float* __restrict__ b,
              const float* __restrict__ gam, const float* __restrict__ bet,
              float* __restrict__ out)
{
    const int t = blockIdx.x, tid = threadIdx.x;
    float v0 = a[(long long)t*Dm + tid]       + b[(long long)t*Dm + tid];
    float v1 = a[(long long)t*Dm + tid + 256] + b[(long long)t*Dm + tid + 256];
    float s = blockReduceSum256(v0 + v1);
    float mean = s * (1.0f / Dm);
    float d0 = v0 - mean, d1 = v1 - mean;
    float sq = blockReduceSum256(d0*d0 + d1*d1);
    float rstd = rsqrtf(sq * (1.0f / Dm) + 1e-5f);
    out[(long long)t*Dm + tid]       = d0 * rstd * gam[tid]       + bet[tid];
    out[(long long)t*Dm + tid + 256] = d1 * rstd * gam[tid + 256] + bet[tid + 256];
}

// logits = gh @ gW2 + gb2 ; 32 tokens/block, 8 experts/token
__global__ void __launch_bounds__(256)
gate_logits_kernel(const float* __restrict__ gW2, const float* __restrict__ gb2)
{
    const int t = blockIdx.x * 32 + (threadIdx.x >> 3);
    const int e = threadIdx.x & 7;
    const float* row = g_gh + (long long)t * Dm;
    float s = 0.f;
    #pragma unroll 8
    for (int d = 0; d < Dm; d++) s += row[d] * gW2[d*Ee + e];
    g_logits[t*Ee + e] = s + gb2[e];
}

__global__ void init_kernel(float* __restrict__ loss)
{
    if (threadIdx.x < Ee) g_cnt[threadIdx.x] = 0;
    if (threadIdx.x == 0) *loss = 0.0f;
}

// top-2 + renormalized softmax weights + expert gather lists
__global__ void __launch_bounds__(256)
topk_kernel()
{
    const int t = blockIdx.x * 256 + threadIdx.x;
    if (t >= Tt) return;
    float lg[Ee];
    #pragma unroll
    for (int e = 0; e < Ee; e++) lg[e] = g_logits[t*Ee + e];
    int i1 = 0;
    #pragma unroll
    for (int e = 1; e < Ee; e++) if (lg[e] > lg[i1]) i1 = e;
    int i2 = -1;
    #pragma unroll
    for (int e = 0; e < Ee; e++) if (e != i1 && (i2 < 0 || lg[e] > lg[i2])) i2 = e;
    float mx = lg[i1];
    float s = 0.f;
    #pragma unroll
    for (int e = 0; e < Ee; e++) s += __expf(lg[e] - mx);
    float p1 = __expf(lg[i1] - mx) / s;
    float p2 = __expf(lg[i2] - mx) / s;
    float dn = p1 + p2 + 1e-9f;
    g_wk[2*t + 0] = p1 / dn;
    g_wk[2*t + 1] = p2 / dn;
    int s1 = atomicAdd(&g_cnt[i1], 1); g_list[i1*Tt + s1] = 2*t + 0;
    int s2 = atomicAdd(&g_cnt[i2], 1); g_list[i2*Tt + s2] = 2*t + 1;
}

// gathered expert FFN layer 1: eh[ent] = gelu(x1[tok] @ eW1[e] + eb1[e])
// grid = (Fd/64, Tt/64, Ee), early-exit beyond count
__global__ void __launch_bounds__(256)
expert_gemm1_kernel(const float* __restrict__ eW1, const float* __restrict__ eb1)
{
    const int e = blockIdx.z;
    const int cnt = g_cnt[e];
    const int r0 = blockIdx.y * 64;
    if (r0 >= cnt) return;
    __shared__ int toks[64];
    __shared__ float As[16][65];
    __shared__ float Bs[16][68];
    const int tid = threadIdx.x, tx = tid & 15, ty = tid >> 4;
    if (tid < 64) {
        int r = r0 + tid;
        toks[tid] = (r < cnt) ? g_list[e*Tt + r] : -1;
    }
    __syncthreads();
    const int n0 = blockIdx.x * 64;
    const int am = tid >> 2, ak = (tid & 3) * 4;
    const int bk = tid >> 4, bn = (tid & 15) * 4;
    const int entA = toks[am];
    const float* Ap = g_x1 + (long long)(entA >= 0 ? (entA >> 1) : 0) * Dm + ak;
    const float* Wp = eW1 + (long long)e*Dm*Fd + (long long)bk*Fd + n0 + bn;
    const float* bp = eb1 + (long long)e*Fd;
    float acc[4][4] = {};
    for (int k0 = 0; k0 < Dm; k0 += 16) {
        float4 a4 = (entA >= 0) ? *(const float4*)(Ap + k0) : make_float4(0,0,0,0);
        As[ak+0][am] = a4.x; As[ak+1][am] = a4.y; As[ak+2][am] = a4.z; As[ak+3][am] = a4.w;
        float4 b4 = *(const float4*)(Wp + (long long)k0 * Fd);
        *(float4*)&Bs[bk][bn] = b4;
        __syncthreads();
        #pragma unroll
        for (int kk = 0; kk < 16; kk++) {
            float a[4], b2[4];
            #pragma unroll
            for (int i = 0; i < 4; i++) a[i] = As[kk][ty*4 + i];
            #pragma unroll
            for (int j = 0; j < 4; j++) b2[j] = Bs[kk][tx*4 + j];
            #pragma unroll
            for (int i = 0; i < 4; i++)
                #pragma unroll
                for (int j = 0; j < 4; j++) acc[i][j] += a[i] * b2[j];
        }
        __syncthreads();
    }
    #pragma unroll
    for (int i = 0; i < 4; i++) {
        int ent = toks[ty*4 + i];
        if (ent < 0) continue;
        #pragma unroll
        for (int j = 0; j < 4; j++) {
            int n = n0 + tx*4 + j;
            g_eh[(long long)ent*Fd + n] = gelu_tanh(acc[i][j] + bp[n]);
        }
    }
}

// gathered expert FFN layer 2: y[ent] = eh[ent] @ eW2[e] + eb2[e]
// grid = (Dm/64, Tt/64, Ee)
__global__ void __launch_bounds__(256)
expert_gemm2_kernel(const float* __restrict__ eW2, const float* __restrict__ eb2)
{
    const int e = blockIdx.z;
    const int cnt = g_cnt[e];
    const int r0 = blockIdx.y * 64;
    if (r0 >= cnt) return;
    __shared__ int toks[64];
    __shared__ float As[16][65];
    __shared__ float Bs[16][68];
    const int tid = threadIdx.x, tx = tid & 15, ty = tid >> 4;
    if (tid < 64) {
        int r = r0 + tid;
        toks[tid] = (r < cnt) ? g_list[e*Tt + r] : -1;
    }
    __syncthreads();
    const int n0 = blockIdx.x * 64;
    const int am = tid >> 2, ak = (tid & 3) * 4;
    const int bk = tid >> 4, bn = (tid & 15) * 4;
    const int entA = toks[am];
    const float* Ap = g_eh + (long long)(entA >= 0 ? entA : 0) * Fd + ak;
    const float* Wp = eW2 + (long long)e*Fd*Dm + (long long)bk*Dm + n0 + bn;
    const float* bp = eb2 + (long long)e*Dm;
    float acc[4][4] = {};
    for (int k0 = 0; k0 < Fd; k0 += 16) {
        float4 a4 = (entA >= 0) ? *(const float4*)(Ap + k0) : make_float4(0,0,0,0);
        As[ak+0][am] = a4.x; As[ak+1][am] = a4.y; As[ak+2][am] = a4.z; As[ak+3][am] = a4.w;
        float4 b4 = *(const float4*)(Wp + (long long)k0 * Dm);
        *(float4*)&Bs[bk][bn] = b4;
        __syncthreads();
        #pragma unroll
        for (int kk = 0; kk < 16; kk++) {
            float a[4], b2[4];
            #pragma unroll
            for (int i = 0; i < 4; i++) a[i] = As[kk][ty*4 + i];
            #pragma unroll
            for (int j = 0; j < 4; j++) b2[j] = Bs[kk][tx*4 + j];
            #pragma unroll
            for (int i = 0; i < 4; i++)
                #pragma unroll
                for (int j = 0; j < 4; j++) acc[i][j] += a[i] * b2[j];
        }
        __syncthreads();
    }
    #pragma unroll
    for (int i = 0; i < 4; i++) {
        int ent = toks[ty*4 + i];
        if (ent < 0) continue;
        #pragma unroll
        for (int j = 0; j < 4; j++) {
            int n = n0 + tx*4 + j;
            g_y[(long long)ent*Dm + n] = acc[i][j] + bp[n];
        }
    }
}

// final: out = LN( gen + bf16(w0*y0 + w1*y1) + x1 ), one block per token
__global__ void __launch_bounds__(256)
final_ln_kernel(const float* __restrict__ gam, const float* __restrict__ bet,
                float* __restrict__ out)
{
    const int t = blockIdx.x, tid = threadIdx.x;
    const float w0 = g_wk[2*t], w1 = g_wk[2*t + 1];
    float vv[2];
    #pragma unroll
    for (int i = 0; i < 2; i++) {
        int d = tid + i*256;
        float moe = w0 * g_y[(long long)(2*t)   * Dm + d]
                  + w1 * g_y[(long long)(2*t+1) * Dm + d];
        moe = __bfloat162float(__float2bfloat16(moe));   // match reference bf16 cast
        vv[i] = g_gen[(long long)t*Dm + d] + moe + g_x1[(long long)t*Dm + d];
    }
    float s = blockReduceSum256(vv[0] + vv[1]);
    float mean = s * (1.0f / Dm);
    float d0 = vv[0] - mean, d1 = vv[1] - mean;
    float sq = blockReduceSum256(d0*d0 + d1*d1);
    float rstd = rsqrtf(sq * (1.0f / Dm) + 1e-5f);
    out[(long long)t*Dm + tid]       = d0 * rstd * gam[tid]       + bet[tid];
    out[(long long)t*Dm + tid + 256] = d1 * rstd * gam[tid + 256] + bet[tid + 256];
}

// ------------------------------- launch -------------------------------------
extern "C" void kernel_launch(void* const* d_in, const int* in_sizes, int n_in,
                              void* d_out, int out_size)
{
    const float* x    = (const float*)d_in[0];
    const float* Wq   = (const float*)d_in[1];
    const float* bq   = (const float*)d_in[2];
    const float* Wk   = (const float*)d_in[3];
    const float* bk   = (const float*)d_in[4];
    const float* Wv   = (const float*)d_in[5];
    const float* bv   = (const float*)d_in[6];
    const float* Wo   = (const float*)d_in[7];
    const float* bo   = (const float*)d_in[8];
    const float* ln1g = (const float*)d_in[9];
    const float* ln1b = (const float*)d_in[10];
    const float* gW1  = (const float*)d_in[11];
    const float* gb1  = (const float*)d_in[12];
    const float* gW2  = (const float*)d_in[13];
    const float* gb2  = (const float*)d_in[14];
    const float* eW1  = (const float*)d_in[15];
    const float* eb1  = (const float*)d_in[16];
    const float* eW2  = (const float*)d_in[17];
    const float* eb2  = (const float*)d_in[18];
    const float* geW1 = (const float*)d_in[19];
    const float* geb1 = (const float*)d_in[20];
    const float* geW2 = (const float*)d_in[21];
    const float* geb2 = (const float*)d_in[22];
    const float* ln2g = (const float*)d_in[23];
    const float* ln2b = (const float*)d_in[24];

    float* out  = (float*)d_out;
    float* attn = out + ATTN_OFF;
    float* loss = out + LOSS_OFF;

    float *pq, *pk, *pv, *pctx, *ptmp, *px1, *pgh, *pgenh, *pgen;
    cudaGetSymbolAddress((void**)&pq,    g_q);
    cudaGetSymbolAddress((void**)&pk,    g_k);
    cudaGetSymbolAddress((void**)&pv,    g_v);
    cudaGetSymbolAddress((void**)&pctx,  g_ctx);
    cudaGetSymbolAddress((void**)&ptmp,  g_tmp);
    cudaGetSymbolAddress((void**)&px1,   g_x1);
    cudaGetSymbolAddress((void**)&pgh,   g_gh);
    cudaGetSymbolAddress((void**)&pgenh, g_genh);
    cudaGetSymbolAddress((void**)&pgen,  g_gen);

    dim3 blk(256);

    // QKV projections
    gemm_bias_kernel<0><<<dim3(Dm/64, Tt/64), blk>>>(x, Wq, bq, pq, Dm, Dm);
    gemm_bias_kernel<0><<<dim3(Dm/64, Tt/64), blk>>>(x, Wk, bk, pk, Dm, Dm);
    gemm_bias_kernel<0><<<dim3(Dm/64, Tt/64), blk>>>(x, Wv, bv, pv, Dm, Dm);

    // attention
    attn_scores_kernel<<<dim3(Ls/64, Ls/64, Bb*Hh), blk>>>(pq, pk, attn);
    softmax_kernel<<<Bb*Hh*Ls, blk>>>(attn);
    attn_v_kernel<<<dim3(1, Ls/64, Bb*Hh), blk>>>(attn, pv, pctx);
    gemm_bias_kernel<0><<<dim3(Dm/64, Tt/64), blk>>>(pctx, Wo, bo, ptmp, Dm, Dm);
    add_ln_kernel<<<Tt, blk>>>(x, ptmp, ln1g, ln1b, px1);

    // gate
    gemm_bias_kernel<1><<<dim3(Dm/64, Tt/64), blk>>>(px1, gW1, gb1, pgh, Dm, Dm);
    gate_logits_kernel<<<Tt/32, blk>>>(gW2, gb2);
    init_kernel<<<1, 32>>>(loss);
    topk_kernel<<<Tt/256, blk>>>();

    // routed experts (sparse top-2 gather)
    expert_gemm1_kernel<<<dim3(Fd/64, Tt/64, Ee), blk>>>(eW1, eb1);
    expert_gemm2_kernel<<<dim3(Dm/64, Tt/64, Ee), blk>>>(eW2, eb2);

    // general expert
    gemm_bias_kernel<1><<<dim3(Fd/64, Tt/64), blk>>>(px1, geW1, geb1, pgenh, Fd, Dm);
    gemm_bias_kernel<0><<<dim3(Dm/64, Tt/64), blk>>>(pgenh, geW2, geb2, pgen, Dm, Fd);

    // combine + LN2 -> out
    final_ln_kernel<<<Tt, blk>>>(ln2g, ln2b, out);
}

// round 4
// speedup vs baseline: 1.7679x; 1.7679x over previous
#include <cuda_runtime.h>
#include <cuda_bf16.h>
#include <cstdint>

// ---------------------------------------------------------------------------
// MoEEncoderLayer: B=2 L=2048 D=512 H=8 E=8 K=2 DF=2048
// Output layout in d_out (float32): [out: T*D][attn: B*H*L*L][aug_loss: 1]
// GEMMs: bf16x3 split-precision mma.sync m16n8k16 (fp32 accumulate).
//   A*B ~= Ah*Bh + Al*Bh + Ah*Bl  with  x = hi(bf16) + lo(bf16)
// ---------------------------------------------------------------------------

#define Bb 2
#define Ls 2048
#define Dm 512
#define Hh 8
#define Ee 8
#define KTOP 2
#define Fd 2048
#define Hd 64
#define Tt (Bb*Ls)                      // 4096

static const long long ATTN_OFF = (long long)Tt * Dm;                      // 2097152
static const long long LOSS_OFF = ATTN_OFF + (long long)Bb*Hh*Ls*Ls;       // 69206016

// ------------------------- scratch (device globals) ------------------------
__device__ float g_q[Tt*Dm];
__device__ float g_k[Tt*Dm];
__device__ float g_v[Tt*Dm];
__device__ float g_ctx[Tt*Dm];
__device__ float g_tmp[Tt*Dm];
__device__ float g_x1[Tt*Dm];
__device__ float g_gh[Tt*Dm];
__device__ float g_logits[Tt*Ee];
__device__ float g_wk[Tt*KTOP];
__device__ int   g_cnt[Ee];
__device__ int   g_list[Ee*Tt];
__device__ float g_eh[Tt*KTOP*Fd];
__device__ float g_y[Tt*KTOP*Dm];
__device__ float g_genh[Tt*Fd];
__device__ float g_gen[Tt*Dm];

// ------------------------------- helpers -----------------------------------
__device__ __forceinline__ float gelu_tanh(float x) {
    float x3 = x * x * x;
    float t  = tanhf(0.7978845608028654f * (x + 0.044715f * x3));
    return 0.5f * x * (1.0f + t);
}

// split fp32 -> (hi, lo) bf16 pair
__device__ __forceinline__ void bsplit(float x, unsigned short& h, unsigned short& l) {
    __nv_bfloat16 hb = __float2bfloat16_rn(x);
    float hf = __bfloat162float(hb);
    __nv_bfloat16 lb = __float2bfloat16_rn(x - hf);
    h = __bfloat16_as_ushort(hb);
    l = __bfloat16_as_ushort(lb);
}
// split two floats and pack the two hi's / lo's into u32 each
__device__ __forceinline__ void bsplit2(float x0, float x1, uint32_t& hp, uint32_t& lp) {
    unsigned short h0, l0, h1, l1;
    bsplit(x0, h0, l0);
    bsplit(x1, h1, l1);
    hp = (uint32_t)h0 | ((uint32_t)h1 << 16);
    lp = (uint32_t)l0 | ((uint32_t)l1 << 16);
}

__device__ __forceinline__ void mma16(float* c, const uint32_t* a, const uint32_t* b) {
    asm volatile(
        "mma.sync.aligned.m16n8k16.row.col.f32.bf16.bf16.f32 "
        "{%0,%1,%2,%3}, {%4,%5,%6,%7}, {%8,%9}, {%0,%1,%2,%3};"
        : "+f"(c[0]), "+f"(c[1]), "+f"(c[2]), "+f"(c[3])
        : "r"(a[0]), "r"(a[1]), "r"(a[2]), "r"(a[3]), "r"(b[0]), "r"(b[1]));
}

__device__ __forceinline__ float warpReduceSum(float v) {
    #pragma unroll
    for (int o = 16; o > 0; o >>= 1) v += __shfl_xor_sync(0xffffffffu, v, o);
    return v;
}
__device__ __forceinline__ float warpReduceMax(float v) {
    #pragma unroll
    for (int o = 16; o > 0; o >>= 1) v = fmaxf(v, __shfl_xor_sync(0xffffffffu, v, o));
    return v;
}
__device__ __forceinline__ float blockReduceSum256(float v) {
    __shared__ float sh[33];
    int tid = threadIdx.x, lane = tid & 31, wid = tid >> 5;
    v = warpReduceSum(v);
    if (lane == 0) sh[wid] = v;
    __syncthreads();
    if (tid < 8) {
        float x = sh[tid];
        #pragma unroll
        for (int o = 4; o > 0; o >>= 1) x += __shfl_xor_sync(0xffu, x, o);
        if (tid == 0) sh[32] = x;
    }
    __syncthreads();
    float r = sh[32];
    __syncthreads();
    return r;
}
__device__ __forceinline__ float blockReduceMax256(float v) {
    __shared__ float sh[33];
    int tid = threadIdx.x, lane = tid & 31, wid = tid >> 5;
    v = warpReduceMax(v);
    if (lane == 0) sh[wid] = v;
    __syncthreads();
    if (tid < 8) {
        float x = sh[tid];
        #pragma unroll
        for (int o = 4; o > 0; o >>= 1) x = fmaxf(x, __shfl_xor_sync(0xffu, x, o));
        if (tid == 0) sh[32] = x;
    }
    __syncthreads();
    float r = sh[32];
    __syncthreads();
    return r;
}

// Fragment loads: A tile stored [row][k] (20 ushorts/row), B tile stored [col][k].
#define LOAD_AFRAG(dst, SA, r_, tg_)                                      \
    dst[0] = *(const uint32_t*)&SA[r_][2*(tg_)];                          \
    dst[1] = *(const uint32_t*)&SA[(r_) + 8][2*(tg_)];                    \
    dst[2] = *(const uint32_t*)&SA[r_][2*(tg_) + 8];                      \
    dst[3] = *(const uint32_t*)&SA[(r_) + 8][2*(tg_) + 8];

#define LOAD_BFRAG(dst, SB, c_, tg_)                                      \
    dst[0] = *(const uint32_t*)&SB[c_][2*(tg_)];                          \
    dst[1] = *(const uint32_t*)&SB[c_][2*(tg_) + 8];

// =====================  generic bf16x3 MMA GEMM  ============================
// C[M x N] = act(A @ W + bias).  A row-major [M x Kd], W row-major [Kd x N].
// Block tile 128x128, K-step 16, 256 threads (8 warps, 4m x 2n, warp 32x64).
template<int ACT>
__global__ void __launch_bounds__(256)
mma_gemm_kernel(const float* __restrict__ A, const float* __restrict__ W,
                const float* __restrict__ bias, float* __restrict__ C,
                int N, int Kd)
{
    __shared__ unsigned short As_hi[2][128][20];
    __shared__ unsigned short As_lo[2][128][20];
    __shared__ unsigned short Bs_hi[2][128][20];   // [n][k]
    __shared__ unsigned short Bs_lo[2][128][20];

    const int tid = threadIdx.x, lane = tid & 31, wid = tid >> 5;
    const int g = lane >> 2, tg = lane & 3;
    const int wm = (wid & 3) * 32, wn = (wid >> 2) * 64;
    const int m0 = blockIdx.y * 128, n0 = blockIdx.x * 128;

    const int lm = tid >> 1, lk = (tid & 1) * 8;
    const int bkr = tid >> 4, bnc = (tid & 15) * 4;

    const float* Ap = A + (long long)(m0 + lm) * Kd + lk;
    const float* Wp = W + (long long)bkr * N + n0 + bnc;

    float acc[2][8][4];
    #pragma unroll
    for (int i = 0; i < 2; i++)
        #pragma unroll
        for (int j = 0; j < 8; j++)
            #pragma unroll
            for (int q = 0; q < 4; q++) acc[i][j][q] = 0.f;

    // prologue: stage 0
    {
        float4 a0 = *(const float4*)(Ap);
        float4 a1 = *(const float4*)(Ap + 4);
        float av[8] = {a0.x,a0.y,a0.z,a0.w,a1.x,a1.y,a1.z,a1.w};
        #pragma unroll
        for (int i = 0; i < 8; i += 2) {
            uint32_t hp, lp;
            bsplit2(av[i], av[i+1], hp, lp);
            *(uint32_t*)&As_hi[0][lm][lk+i] = hp;
            *(uint32_t*)&As_lo[0][lm][lk+i] = lp;
        }
        float4 w0 = *(const float4*)(Wp);
        float4 w1 = *(const float4*)(Wp + 64);
        float wv0[4] = {w0.x,w0.y,w0.z,w0.w};
        float wv1[4] = {w1.x,w1.y,w1.z,w1.w};
        #pragma unroll
        for (int i = 0; i < 4; i++) {
            unsigned short h, l;
            bsplit(wv0[i], h, l);
            Bs_hi[0][bnc+i][bkr] = h; Bs_lo[0][bnc+i][bkr] = l;
            bsplit(wv1[i], h, l);
            Bs_hi[0][bnc+i+64][bkr] = h; Bs_lo[0][bnc+i+64][bkr] = l;
        }
    }
    __syncthreads();

    const int nit = Kd / 16;
    for (int it = 0; it < nit; it++) {
        float4 na0, na1, nw0, nw1;
        if (it + 1 < nit) {
            const float* Ap2 = Ap + (it + 1) * 16;
            na0 = *(const float4*)(Ap2);
            na1 = *(const float4*)(Ap2 + 4);
            const float* Wp2 = Wp + (long long)(it + 1) * 16 * N;
            nw0 = *(const float4*)(Wp2);
            nw1 = *(const float4*)(Wp2 + 64);
        }
        const int cur = it & 1;
        uint32_t ah[2][4], al[2][4];
        #pragma unroll
        for (int mi = 0; mi < 2; mi++) {
            const int r = wm + mi * 16 + g;
            LOAD_AFRAG(ah[mi], As_hi[cur], r, tg);
            LOAD_AFRAG(al[mi], As_lo[cur], r, tg);
        }
        #pragma unroll
        for (int nj = 0; nj < 8; nj++) {
            const int c = wn + nj * 8 + g;
            uint32_t bh[2], bl[2];
            LOAD_BFRAG(bh, Bs_hi[cur], c, tg);
            LOAD_BFRAG(bl, Bs_lo[cur], c, tg);
            mma16(acc[0][nj], ah[0], bh);
            mma16(acc[1][nj], ah[1], bh);
            mma16(acc[0][nj], al[0], bh);
            mma16(acc[1][nj], al[1], bh);
            mma16(acc[0][nj], ah[0], bl);
            mma16(acc[1][nj], ah[1], bl);
        }
        if (it + 1 < nit) {
            const int nx = (it + 1) & 1;
            float av[8] = {na0.x,na0.y,na0.z,na0.w,na1.x,na1.y,na1.z,na1.w};
            #pragma unroll
            for (int i = 0; i < 8; i += 2) {
                uint32_t hp, lp;
                bsplit2(av[i], av[i+1], hp, lp);
                *(uint32_t*)&As_hi[nx][lm][lk+i] = hp;
                *(uint32_t*)&As_lo[nx][lm][lk+i] = lp;
            }
            float wv0[4] = {nw0.x,nw0.y,nw0.z,nw0.w};
            float wv1[4] = {nw1.x,nw1.y,nw1.z,nw1.w};
            #pragma unroll
            for (int i = 0; i < 4; i++) {
                unsigned short h, l;
                bsplit(wv0[i], h, l);
                Bs_hi[nx][bnc+i][bkr] = h; Bs_lo[nx][bnc+i][bkr] = l;
                bsplit(wv1[i], h, l);
                Bs_hi[nx][bnc+i+64][bkr] = h; Bs_lo[nx][bnc+i+64][bkr] = l;
            }
        }
        __syncthreads();
    }

    #pragma unroll
    for (int mi = 0; mi < 2; mi++) {
        const int r0 = m0 + wm + mi * 16 + g;
        #pragma unroll
        for (int nj = 0; nj < 8; nj++) {
            const int c = n0 + wn + nj * 8 + tg * 2;
            const float b0v = bias[c], b1v = bias[c + 1];
            float v0 = acc[mi][nj][0] + b0v, v1 = acc[mi][nj][1] + b1v;
            float v2 = acc[mi][nj][2] + b0v, v3 = acc[mi][nj][3] + b1v;
            if (ACT) { v0 = gelu_tanh(v0); v1 = gelu_tanh(v1); v2 = gelu_tanh(v2); v3 = gelu_tanh(v3); }
            *(float2*)&C[(long long)r0 * N + c]       = make_float2(v0, v1);
            *(float2*)&C[(long long)(r0 + 8) * N + c] = make_float2(v2, v3);
        }
    }
}

// ==================  gathered expert GEMMs (bf16x3 MMA)  ====================
// MODE 0: eh[ent] = gelu(x1[ent>>1] @ eW1[e] + eb1[e])   (N=Fd, Kd=Dm)
// MODE 1: y[ent]  = eh[ent] @ eW2[e] + eb2[e]            (N=Dm, Kd=Fd)
template<int MODE>
__global__ void __launch_bounds__(256)
mma_expert_kernel(const float* __restrict__ Wmat, const float* __restrict__ bias)
{
    const int e = blockIdx.z;
    const int cnt = g_cnt[e];
    const int r0blk = blockIdx.y * 128;
    if (r0blk >= cnt) return;

    const int N  = MODE ? Dm : Fd;
    const int Kd = MODE ? Fd : Dm;

    __shared__ unsigned short As_hi[2][128][20];
    __shared__ unsigned short As_lo[2][128][20];
    __shared__ unsigned short Bs_hi[2][128][20];
    __shared__ unsigned short Bs_lo[2][128][20];
    __shared__ int toks[128];

    const int tid = threadIdx.x, lane = tid & 31, wid = tid >> 5;
    const int g = lane >> 2, tg = lane & 3;
    const int wm = (wid & 3) * 32, wn = (wid >> 2) * 64;
    const int n0 = blockIdx.x * 128;

    if (tid < 128) {
        int r = r0blk + tid;
        toks[tid] = (r < cnt) ? g_list[e * Tt + r] : -1;
    }
    __syncthreads();

    const int lm = tid >> 1, lk = (tid & 1) * 8;
    const int bkr = tid >> 4, bnc = (tid & 15) * 4;

    const int entA = toks[lm];
    long long arow;
    const float* Abase;
    if (MODE == 0) { arow = (entA >= 0) ? (long long)(entA >> 1) : 0; Abase = g_x1; }
    else           { arow = (entA >= 0) ? (long long)entA        : 0; Abase = g_eh; }
    const float* Ap = Abase + arow * Kd + lk;
    const float* Wp = Wmat + (long long)e * Dm * Fd + (long long)bkr * N + n0 + bnc;
    const float* bp = bias + (long long)e * N;

    float acc[2][8][4];
    #pragma unroll
    for (int i = 0; i < 2; i++)
        #pragma unroll
        for (int j = 0; j < 8; j++)
            #pragma unroll
            for (int q = 0; q < 4; q++) acc[i][j][q] = 0.f;

    {
        float4 a0 = *(const float4*)(Ap);
        float4 a1 = *(const float4*)(Ap + 4);
        float av[8] = {a0.x,a0.y,a0.z,a0.w,a1.x,a1.y,a1.z,a1.w};
        #pragma unroll
        for (int i = 0; i < 8; i += 2) {
            uint32_t hp, lp;
            bsplit2(av[i], av[i+1], hp, lp);
            *(uint32_t*)&As_hi[0][lm][lk+i] = hp;
            *(uint32_t*)&As_lo[0][lm][lk+i] = lp;
        }
        float4 w0 = *(const float4*)(Wp);
        float4 w1 = *(const float4*)(Wp + 64);
        float wv0[4] = {w0.x,w0.y,w0.z,w0.w};
        float wv1[4] = {w1.x,w1.y,w1.z,w1.w};
        #pragma unroll
        for (int i = 0; i < 4; i++) {
            unsigned short h, l;
            bsplit(wv0[i], h, l);
            Bs_hi[0][bnc+i][bkr] = h; Bs_lo[0][bnc+i][bkr] = l;
            bsplit(wv1[i], h, l);
            Bs_hi[0][bnc+i+64][bkr] = h; Bs_lo[0][bnc+i+64][bkr] = l;
        }
    }
    __syncthreads();

    const int nit = Kd / 16;
    for (int it = 0; it < nit; it++) {
        float4 na0, na1, nw0, nw1;
        if (it + 1 < nit) {
            const float* Ap2 = Ap + (it + 1) * 16;
            na0 = *(const float4*)(Ap2);
            na1 = *(const float4*)(Ap2 + 4);
            const float* Wp2 = Wp + (long long)(it + 1) * 16 * N;
            nw0 = *(const float4*)(Wp2);
            nw1 = *(const float4*)(Wp2 + 64);
        }
        const int cur = it & 1;
        uint32_t ah[2][4], al[2][4];
        #pragma unroll
        for (int mi = 0; mi < 2; mi++) {
            const int r = wm + mi * 16 + g;
            LOAD_AFRAG(ah[mi], As_hi[cur], r, tg);
            LOAD_AFRAG(al[mi], As_lo[cur], r, tg);
        }
        #pragma unroll
        for (int nj = 0; nj < 8; nj++) {
            const int c = wn + nj * 8 + g;
            uint32_t bh[2], bl[2];
            LOAD_BFRAG(bh, Bs_hi[cur], c, tg);
            LOAD_BFRAG(bl, Bs_lo[cur], c, tg);
            mma16(acc[0][nj], ah[0], bh);
            mma16(acc[1][nj], ah[1], bh);
            mma16(acc[0][nj], al[0], bh);
            mma16(acc[1][nj], al[1], bh);
            mma16(acc[0][nj], ah[0], bl);
            mma16(acc[1][nj], ah[1], bl);
        }
        if (it + 1 < nit) {
            const int nx = (it + 1) & 1;
            float av[8] = {na0.x,na0.y,na0.z,na0.w,na1.x,na1.y,na1.z,na1.w};
            #pragma unroll
            for (int i = 0; i < 8; i += 2) {
                uint32_t hp, lp;
                bsplit2(av[i], av[i+1], hp, lp);
                *(uint32_t*)&As_hi[nx][lm][lk+i] = hp;
                *(uint32_t*)&As_lo[nx][lm][lk+i] = lp;
            }
            float wv0[4] = {nw0.x,nw0.y,nw0.z,nw0.w};
            float wv1[4] = {nw1.x,nw1.y,nw1.z,nw1.w};
            #pragma unroll
            for (int i = 0; i < 4; i++) {
                unsigned short h, l;
                bsplit(wv0[i], h, l);
                Bs_hi[nx][bnc+i][bkr] = h; Bs_lo[nx][bnc+i][bkr] = l;
                bsplit(wv1[i], h, l);
                Bs_hi[nx][bnc+i+64][bkr] = h; Bs_lo[nx][bnc+i+64][bkr] = l;
            }
        }
        __syncthreads();
    }

    float* Cout = MODE ? g_y : g_eh;
    #pragma unroll
    for (int mi = 0; mi < 2; mi++) {
        const int rr0 = wm + mi * 16 + g;
        const int ent0 = toks[rr0], ent1 = toks[rr0 + 8];
        #pragma unroll
        for (int nj = 0; nj < 8; nj++) {
            const int c = wn + nj * 8 + tg * 2;
            const float b0v = bp[n0 + c], b1v = bp[n0 + c + 1];
            if (ent0 >= 0) {
                float v0 = acc[mi][nj][0] + b0v, v1 = acc[mi][nj][1] + b1v;
                if (MODE == 0) { v0 = gelu_tanh(v0); v1 = gelu_tanh(v1); }
                *(float2*)&Cout[(long long)ent0 * N + n0 + c] = make_float2(v0, v1);
            }
            if (ent1 >= 0) {
                float v2 = acc[mi][nj][2] + b0v, v3 = acc[mi][nj][3] + b1v;
                if (MODE == 0) { v2 = gelu_tanh(v2); v3 = gelu_tanh(v3); }
                *(float2*)&Cout[(long long)ent1 * N + n0 + c] = make_float2(v2, v3);
            }
        }
    }
}

// ================  attention scores (bf16x3 MMA): Q K^T / 8  ================
// grid = (L/128, L/128, B*H), 256 thr.  Kd = 64 (head dim).
__global__ void __launch_bounds__(256)
mma_scores_kernel(const float* __restrict__ q, const float* __restrict__ k,
                  float* __restrict__ attn)
{
    __shared__ unsigned short As_hi[2][128][20];
    __shared__ unsigned short As_lo[2][128][20];
    __shared__ unsigned short Bs_hi[2][128][20];   // [key][k]
    __shared__ unsigned short Bs_lo[2][128][20];

    const int tid = threadIdx.x, lane = tid & 31, wid = tid >> 5;
    const int g = lane >> 2, tg = lane & 3;
    const int wm = (wid & 3) * 32, wn = (wid >> 2) * 64;
    const int bh = blockIdx.z; const int b = bh >> 3, h = bh & 7;
    const int i0 = blockIdx.y * 128, j0 = blockIdx.x * 128;

    const int lm = tid >> 1, lk = (tid & 1) * 8;

    const float* Qp = q + (long long)(b * Ls + i0 + lm) * Dm + h * Hd + lk;
    const float* Kp = k + (long long)(b * Ls + j0 + lm) * Dm + h * Hd + lk;

    float acc[2][8][4];
    #pragma unroll
    for (int i = 0; i < 2; i++)
        #pragma unroll
        for (int j = 0; j < 8; j++)
            #pragma unroll
            for (int q2 = 0; q2 < 4; q2++) acc[i][j][q2] = 0.f;

    {
        float4 a0 = *(const float4*)(Qp);
        float4 a1 = *(const float4*)(Qp + 4);
        float av[8] = {a0.x,a0.y,a0.z,a0.w,a1.x,a1.y,a1.z,a1.w};
        #pragma unroll
        for (int i = 0; i < 8; i += 2) {
            uint32_t hp, lp;
            bsplit2(av[i], av[i+1], hp, lp);
            *(uint32_t*)&As_hi[0][lm][lk+i] = hp;
            *(uint32_t*)&As_lo[0][lm][lk+i] = lp;
        }
        float4 k0 = *(const float4*)(Kp);
        float4 k1 = *(const float4*)(Kp + 4);
        float kv[8] = {k0.x,k0.y,k0.z,k0.w,k1.x,k1.y,k1.z,k1.w};
        #pragma unroll
        for (int i = 0; i < 8; i += 2) {
            uint32_t hp, lp;
            bsplit2(kv[i], kv[i+1], hp, lp);
            *(uint32_t*)&Bs_hi[0][lm][lk+i] = hp;
            *(uint32_t*)&Bs_lo[0][lm][lk+i] = lp;
        }
    }
    __syncthreads();

    const int nit = Hd / 16;      // 4
    for (int it = 0; it < nit; it++) {
        float4 na0, na1, nk0, nk1;
        if (it + 1 < nit) {
            na0 = *(const float4*)(Qp + (it + 1) * 16);
            na1 = *(const float4*)(Qp + (it + 1) * 16 + 4);
            nk0 = *(const float4*)(Kp + (it + 1) * 16);
            nk1 = *(const float4*)(Kp + (it + 1) * 16 + 4);
        }
        const int cur = it & 1;
        uint32_t ah[2][4], al[2][4];
        #pragma unroll
        for (int mi = 0; mi < 2; mi++) {
            const int r = wm + mi * 16 + g;
            LOAD_AFRAG(ah[mi], As_hi[cur], r, tg);
            LOAD_AFRAG(al[mi], As_lo[cur], r, tg);
        }
        #pragma unroll
        for (int nj = 0; nj < 8; nj++) {
            const int c = wn + nj * 8 + g;
            uint32_t bh2[2], bl2[2];
            LOAD_BFRAG(bh2, Bs_hi[cur], c, tg);
            LOAD_BFRAG(bl2, Bs_lo[cur], c, tg);
            mma16(acc[0][nj], ah[0], bh2);
            mma16(acc[1][nj], ah[1], bh2);
            mma16(acc[0][nj], al[0], bh2);
            mma16(acc[1][nj], al[1], bh2);
            mma16(acc[0][nj], ah[0], bl2);
            mma16(acc[1][nj], ah[1], bl2);
        }
        if (it + 1 < nit) {
            const int nx = (it + 1) & 1;
            float av[8] = {na0.x,na0.y,na0.z,na0.w,na1.x,na1.y,na1.z,na1.w};
            #pragma unroll
            for (int i = 0; i < 8; i += 2) {
                uint32_t hp, lp;
                bsplit2(av[i], av[i+1], hp, lp);
                *(uint32_t*)&As_hi[nx][lm][lk+i] = hp;
                *(uint32_t*)&As_lo[nx][lm][lk+i] = lp;
            }
            float kv[8] = {nk0.x,nk0.y,nk0.z,nk0.w,nk1.x,nk1.y,nk1.z,nk1.w};
            #pragma unroll
            for (int i = 0; i < 8; i += 2) {
                uint32_t hp, lp;
                bsplit2(kv[i], kv[i+1], hp, lp);
                *(uint32_t*)&Bs_hi[nx][lm][lk+i] = hp;
                *(uint32_t*)&Bs_lo[nx][lm][lk+i] = lp;
            }
        }
        __syncthreads();
    }

    float* O = attn + (long long)bh * Ls * Ls;
    #pragma unroll
    for (int mi = 0; mi < 2; mi++) {
        const int r0 = i0 + wm + mi * 16 + g;
        #pragma unroll
        for (int nj = 0; nj < 8; nj++) {
            const int c = j0 + wn + nj * 8 + tg * 2;
            *(float2*)&O[(long long)r0 * Ls + c] =
                make_float2(acc[mi][nj][0] * 0.125f, acc[mi][nj][1] * 0.125f);
            *(float2*)&O[(long long)(r0 + 8) * Ls + c] =
                make_float2(acc[mi][nj][2] * 0.125f, acc[mi][nj][3] * 0.125f);
        }
    }
}

// =====================  P @ V (bf16x3 MMA)  =================================
// grid = (1, L/128, B*H).  Block 128x64, warp 32x32, Kd = L = 2048.
__global__ void __launch_bounds__(256)
mma_attnv_kernel(const float* __restrict__ attn, const float* __restrict__ v,
                 float* __restrict__ ctx)
{
    __shared__ unsigned short As_hi[2][128][20];
    __shared__ unsigned short As_lo[2][128][20];
    __shared__ unsigned short Bs_hi[2][64][20];    // [hd-col][k]
    __shared__ unsigned short Bs_lo[2][64][20];

    const int tid = threadIdx.x, lane = tid & 31, wid = tid >> 5;
    const int g = lane >> 2, tg = lane & 3;
    const int wm = (wid & 3) * 32, wn = (wid >> 2) * 32;
    const int bh = blockIdx.z; const int b = bh >> 3, h = bh & 7;
    const int i0 = blockIdx.y * 128;

    const int lm = tid >> 1, lk = (tid & 1) * 8;
    const int bkr = tid >> 4, bnc = (tid & 15) * 4;

    const float* Ap = attn + (long long)bh * Ls * Ls + (long long)(i0 + lm) * Ls + lk;
    const float* Vp = v + (long long)(b * Ls + bkr) * Dm + h * Hd + bnc;

    float acc[2][4][4];
    #pragma unroll
    for (int i = 0; i < 2; i++)
        #pragma unroll
        for (int j = 0; j < 4; j++)
            #pragma unroll
            for (int q = 0; q < 4; q++) acc[i][j][q] = 0.f;

    {
        float4 a0 = *(const float4*)(Ap);
        float4 a1 = *(const float4*)(Ap + 4);
        float av[8] = {a0.x,a0.y,a0.z,a0.w,a1.x,a1.y,a1.z,a1.w};
        #pragma unroll
        for (int i = 0; i < 8; i += 2) {
            uint32_t hp, lp;
            bsplit2(av[i], av[i+1], hp, lp);
            *(uint32_t*)&As_hi[0][lm][lk+i] = hp;
            *(uint32_t*)&As_lo[0][lm][lk+i] = lp;
        }
        float4 w0 = *(const float4*)(Vp);
        float wv[4] = {w0.x,w0.y,w0.z,w0.w};
        #pragma unroll
        for (int i = 0; i < 4; i++) {
            unsigned short hh, ll;
            bsplit(wv[i], hh, ll);
            Bs_hi[0][bnc+i][bkr] = hh; Bs_lo[0][bnc+i][bkr] = ll;
        }
    }
    __syncthreads();

    const int nit = Ls / 16;      // 128
    for (int it = 0; it < nit; it++) {
        float4 na0, na1, nw0;
        if (it + 1 < nit) {
            na0 = *(const float4*)(Ap + (it + 1) * 16);
            na1 = *(const float4*)(Ap + (it + 1) * 16 + 4);
            nw0 = *(const float4*)(Vp + (long long)(it + 1) * 16 * Dm);
        }
        const int cur = it & 1;
        uint32_t ah[2][4], al[2][4];
        #pragma unroll
        for (int mi = 0; mi < 2; mi++) {
            const int r = wm + mi * 16 + g;
            LOAD_AFRAG(ah[mi], As_hi[cur], r, tg);
            LOAD_AFRAG(al[mi], As_lo[cur], r, tg);
        }
        #pragma unroll
        for (int nj = 0; nj < 4; nj++) {
            const int c = wn + nj * 8 + g;
            uint32_t bh2[2], bl2[2];
            LOAD_BFRAG(bh2, Bs_hi[cur], c, tg);
            LOAD_BFRAG(bl2, Bs_lo[cur], c, tg);
            mma16(acc[0][nj], ah[0], bh2);
            mma16(acc[1][nj], ah[1], bh2);
            mma16(acc[0][nj], al[0], bh2);
            mma16(acc[1][nj], al[1], bh2);
            mma16(acc[0][nj], ah[0], bl2);
            mma16(acc[1][nj], ah[1], bl2);
        }
        if (it + 1 < nit) {
            const int nx = (it + 1) & 1;
            float av[8] = {na0.x,na0.y,na0.z,na0.w,na1.x,na1.y,na1.z,na1.w};
            #pragma unroll
            for (int i = 0; i < 8; i += 2) {
                uint32_t hp, lp;
                bsplit2(av[i], av[i+1], hp, lp);
                *(uint32_t*)&As_hi[nx][lm][lk+i] = hp;
                *(uint32_t*)&As_lo[nx][lm][lk+i] = lp;
            }
            float wv[4] = {nw0.x,nw0.y,nw0.z,nw0.w};
            #pragma unroll
            for (int i = 0; i < 4; i++) {
                unsigned short hh, ll;
                bsplit(wv[i], hh, ll);
                Bs_hi[nx][bnc+i][bkr] = hh; Bs_lo[nx][bnc+i][bkr] = ll;
            }
        }
        __syncthreads();
    }

    #pragma unroll
    for (int mi = 0; mi < 2; mi++) {
        const int r0 = b * Ls + i0 + wm + mi * 16 + g;
        #pragma unroll
        for (int nj = 0; nj < 4; nj++) {
            const int c = h * Hd + wn + nj * 8 + tg * 2;
            *(float2*)&ctx[(long long)r0 * Dm + c] =
                make_float2(acc[mi][nj][0], acc[mi][nj][1]);
            *(float2*)&ctx[(long long)(r0 + 8) * Dm + c] =
                make_float2(acc[mi][nj][2], acc[mi][nj][3]);
        }
    }
}

// ======================== elementwise / small kernels =======================
__global__ void __launch_bounds__(256)
softmax_kernel(float* __restrict__ attn)
{
    const long long row = blockIdx.x;
    float* p = attn + row * (long long)Ls;
    const int tid = threadIdx.x;
    float v[8];
    float mx = -1e30f;
    #pragma unroll
    for (int i = 0; i < 8; i++) { v[i] = p[tid + i*256]; mx = fmaxf(mx, v[i]); }
    mx = blockReduceMax256(mx);
    float s = 0.f;
    #pragma unroll
    for (int i = 0; i < 8; i++) { v[i] = __expf(v[i] - mx); s += v[i]; }
    s = blockReduceSum256(s);
    float inv = 1.f / s;
    #pragma unroll
    for (int i = 0; i < 8; i++) p[tid + i*256] = v[i] * inv;
}

__global__ void __launch_bounds__(256)
add_ln_kernel(const float* __restrict__ a, const float* __restrict__ b,
              const float* __restrict__ gam, const float* __restrict__ bet,
              float* __restrict__ out)
{
    const int t = blockIdx.x, tid = threadIdx.x;
    float v0 = a[(long long)t*Dm + tid]       + b[(long long)t*Dm + tid];
    float v1 = a[(long long)t*Dm + tid + 256] + b[(long long)t*Dm + tid + 256];
    float s = blockReduceSum256(v0 + v1);
    float mean = s * (1.0f / Dm);
    float d0 = v0 - mean, d1 = v1 - mean;
    float sq = blockReduceSum256(d0*d0 + d1*d1);
    float rstd = rsqrtf(sq * (1.0f / Dm) + 1e-5f);
    out[(long long)t*Dm + tid]       = d0 * rstd * gam[tid]       + bet[tid];
    out[(long long)t*Dm + tid + 256] = d1 * rstd * gam[tid + 256] + bet[tid + 256];
}

__global__ void __launch_bounds__(256)
gate_logits_kernel(const float* __restrict__ gW2, const float* __restrict__ gb2)
{
    const int t = blockIdx.x * 32 + (threadIdx.x >> 3);
    const int e = threadIdx.x & 7;
    const float* row = g_gh + (long long)t * Dm;
    float s = 0.f;
    #pragma unroll 8
    for (int d = 0; d < Dm; d++) s += row[d] * gW2[d*Ee + e];
    g_logits[t*Ee + e] = s + gb2[e];
}

__global__ void init_kernel(float* __restrict__ loss)
{
    if (threadIdx.x < Ee) g_cnt[threadIdx.x] = 0;
    if (threadIdx.x == 0) *loss = 0.0f;
}

__global__ void __launch_bounds__(256)
topk_kernel()
{
    const int t = blockIdx.x * 256 + threadIdx.x;
    if (t >= Tt) return;
    float lg[Ee];
    #pragma unroll
    for (int e = 0; e < Ee; e++) lg[e] = g_logits[t*Ee + e];
    int i1 = 0;
    #pragma unroll
    for (int e = 1; e < Ee; e++) if (lg[e] > lg[i1]) i1 = e;
    int i2 = -1;
    #pragma unroll
    for (int e = 0; e < Ee; e++) if (e != i1 && (i2 < 0 || lg[e] > lg[i2])) i2 = e;
    float mx = lg[i1];
    float s = 0.f;
    #pragma unroll
    for (int e = 0; e < Ee; e++) s += __expf(lg[e] - mx);
    float p1 = __expf(lg[i1] - mx) / s;
    float p2 = __expf(lg[i2] - mx) / s;
    float dn = p1 + p2 + 1e-9f;
    g_wk[2*t + 0] = p1 / dn;
    g_wk[2*t + 1] = p2 / dn;
    int s1 = atomicAdd(&g_cnt[i1], 1); g_list[i1*Tt + s1] = 2*t + 0;
    int s2 = atomicAdd(&g_cnt[i2], 1); g_list[i2*Tt + s2] = 2*t + 1;
}

__global__ void __launch_bounds__(256)
final_ln_kernel(const float* __restrict__ gam, const float* __restrict__ bet,
                float* __restrict__ out)
{
    const int t = blockIdx.x, tid = threadIdx.x;
    const float w0 = g_wk[2*t], w1 = g_wk[2*t + 1];
    float vv[2];
    #pragma unroll
    for (int i = 0; i < 2; i++) {
        int d = tid + i*256;
        float moe = w0 * g_y[(long long)(2*t)   * Dm + d]
                  + w1 * g_y[(long long)(2*t+1) * Dm + d];
        moe = __bfloat162float(__float2bfloat16(moe));
        vv[i] = g_gen[(long long)t*Dm + d] + moe + g_x1[(long long)t*Dm + d];
    }
    float s = blockReduceSum256(vv[0] + vv[1]);
    float mean = s * (1.0f / Dm);
    float d0 = vv[0] - mean, d1 = vv[1] - mean;
    float sq = blockReduceSum256(d0*d0 + d1*d1);
    float rstd = rsqrtf(sq * (1.0f / Dm) + 1e-5f);
    out[(long long)t*Dm + tid]       = d0 * rstd * gam[tid]       + bet[tid];
    out[(long long)t*Dm + tid + 256] = d1 * rstd * gam[tid + 256] + bet[tid + 256];
}

// ------------------------------- launch -------------------------------------
extern "C" void kernel_launch(void* const* d_in, const int* in_sizes, int n_in,
                              void* d_out, int out_size)
{
    const float* x    = (const float*)d_in[0];
    const float* Wq   = (const float*)d_in[1];
    const float* bq   = (const float*)d_in[2];
    const float* Wk   = (const float*)d_in[3];
    const float* bk   = (const float*)d_in[4];
    const float* Wv   = (const float*)d_in[5];
    const float* bv   = (const float*)d_in[6];
    const float* Wo   = (const float*)d_in[7];
    const float* bo   = (const float*)d_in[8];
    const float* ln1g = (const float*)d_in[9];
    const float* ln1b = (const float*)d_in[10];
    const float* gW1  = (const float*)d_in[11];
    const float* gb1  = (const float*)d_in[12];
    const float* gW2  = (const float*)d_in[13];
    const float* gb2  = (const float*)d_in[14];
    const float* eW1  = (const float*)d_in[15];
    const float* eb1  = (const float*)d_in[16];
    const float* eW2  = (const float*)d_in[17];
    const float* eb2  = (const float*)d_in[18];
    const float* geW1 = (const float*)d_in[19];
    const float* geb1 = (const float*)d_in[20];
    const float* geW2 = (const float*)d_in[21];
    const float* geb2 = (const float*)d_in[22];
    const float* ln2g = (const float*)d_in[23];
    const float* ln2b = (const float*)d_in[24];

    float* out  = (float*)d_out;
    float* attn = out + ATTN_OFF;
    float* loss = out + LOSS_OFF;

    float *pq, *pk, *pv, *pctx, *ptmp, *px1, *pgh, *pgenh, *pgen;
    cudaGetSymbolAddress((void**)&pq,    g_q);
    cudaGetSymbolAddress((void**)&pk,    g_k);
    cudaGetSymbolAddress((void**)&pv,    g_v);
    cudaGetSymbolAddress((void**)&pctx,  g_ctx);
    cudaGetSymbolAddress((void**)&ptmp,  g_tmp);
    cudaGetSymbolAddress((void**)&px1,   g_x1);
    cudaGetSymbolAddress((void**)&pgh,   g_gh);
    cudaGetSymbolAddress((void**)&pgenh, g_genh);
    cudaGetSymbolAddress((void**)&pgen,  g_gen);

    dim3 blk(256);

    // QKV projections (M=4096, N=512, K=512)
    mma_gemm_kernel<0><<<dim3(Dm/128, Tt/128), blk>>>(x, Wq, bq, pq, Dm, Dm);
    mma_gemm_kernel<0><<<dim3(Dm/128, Tt/128), blk>>>(x, Wk, bk, pk, Dm, Dm);
    mma_gemm_kernel<0><<<dim3(Dm/128, Tt/128), blk>>>(x, Wv, bv, pv, Dm, Dm);

    // attention
    mma_scores_kernel<<<dim3(Ls/128, Ls/128, Bb*Hh), blk>>>(pq, pk, attn);
    softmax_kernel<<<Bb*Hh*Ls, blk>>>(attn);
    mma_attnv_kernel<<<dim3(1, Ls/128, Bb*Hh), blk>>>(attn, pv, pctx);
    mma_gemm_kernel<0><<<dim3(Dm/128, Tt/128), blk>>>(pctx, Wo, bo, ptmp, Dm, Dm);
    add_ln_kernel<<<Tt, blk>>>(x, ptmp, ln1g, ln1b, px1);

    // gate
    mma_gemm_kernel<1><<<dim3(Dm/128, Tt/128), blk>>>(px1, gW1, gb1, pgh, Dm, Dm);
    gate_logits_kernel<<<Tt/32, blk>>>(gW2, gb2);
    init_kernel<<<1, 32>>>(loss);
    topk_kernel<<<Tt/256, blk>>>();

    // routed experts (sparse top-2 gather)
    mma_expert_kernel<0><<<dim3(Fd/128, Tt/128, Ee), blk>>>(eW1, eb1);
    mma_expert_kernel<1><<<dim3(Dm/128, Tt/128, Ee), blk>>>(eW2, eb2);

    // general expert
    mma_gemm_kernel<1><<<dim3(Fd/128, Tt/128), blk>>>(px1, geW1, geb1, pgenh, Fd, Dm);
    mma_gemm_kernel<0><<<dim3(Dm/128, Tt/128), blk>>>(pgenh, geW2, geb2, pgen, Dm, Fd);

    // combine + LN2 -> out
    final_ln_kernel<<<Tt, blk>>>(ln2g, ln2b, out);
}

// round 5
// speedup vs baseline: 1.8574x; 1.0506x over previous
#include <cuda_runtime.h>
#include <cuda_bf16.h>
#include <cstdint>

// ---------------------------------------------------------------------------
// MoEEncoderLayer: B=2 L=2048 D=512 H=8 E=8 K=2 DF=2048
// Output layout in d_out (float32): [out: T*D][attn: B*H*L*L][aug_loss: 1]
// GEMMs: bf16x3 split-precision mma.sync m16n8k16 (fp32 accumulate),
// fragments via ldmatrix.x4 from a swizzled conflict-free smem layout.
// ---------------------------------------------------------------------------

#define Bb 2
#define Ls 2048
#define Dm 512
#define Hh 8
#define Ee 8
#define KTOP 2
#define Fd 2048
#define Hd 64
#define Tt (Bb*Ls)                      // 4096

static const long long ATTN_OFF = (long long)Tt * Dm;                      // 2097152
static const long long LOSS_OFF = ATTN_OFF + (long long)Bb*Hh*Ls*Ls;       // 69206016

// ------------------------- scratch (device globals) ------------------------
__device__ float g_q[Tt*Dm];
__device__ float g_k[Tt*Dm];
__device__ float g_v[Tt*Dm];
__device__ float g_ctx[Tt*Dm];
__device__ float g_tmp[Tt*Dm];
__device__ float g_x1[Tt*Dm];
__device__ float g_gh[Tt*Dm];
__device__ float g_logits[Tt*Ee];
__device__ float g_wk[Tt*KTOP];
__device__ int   g_cnt[Ee];
__device__ int   g_list[Ee*Tt];
__device__ float g_eh[Tt*KTOP*Fd];
__device__ float g_y[Tt*KTOP*Dm];
__device__ float g_genh[Tt*Fd];
__device__ float g_gen[Tt*Dm];

// ------------------------------- helpers -----------------------------------
__device__ __forceinline__ float gelu_tanh(float x) {
    float x3 = x * x * x;
    float t  = tanhf(0.7978845608028654f * (x + 0.044715f * x3));
    return 0.5f * x * (1.0f + t);
}

__device__ __forceinline__ void bsplit(float x, unsigned short& h, unsigned short& l) {
    __nv_bfloat16 hb = __float2bfloat16_rn(x);
    float hf = __bfloat162float(hb);
    __nv_bfloat16 lb = __float2bfloat16_rn(x - hf);
    h = __bfloat16_as_ushort(hb);
    l = __bfloat16_as_ushort(lb);
}
__device__ __forceinline__ void bsplit2(float x0, float x1, uint32_t& hp, uint32_t& lp) {
    unsigned short h0, l0, h1, l1;
    bsplit(x0, h0, l0);
    bsplit(x1, h1, l1);
    hp = (uint32_t)h0 | ((uint32_t)h1 << 16);
    lp = (uint32_t)l0 | ((uint32_t)l1 << 16);
}

__device__ __forceinline__ void mma16(float* c, const uint32_t* a, const uint32_t* b) {
    asm volatile(
        "mma.sync.aligned.m16n8k16.row.col.f32.bf16.bf16.f32 "
        "{%0,%1,%2,%3}, {%4,%5,%6,%7}, {%8,%9}, {%0,%1,%2,%3};"
        : "+f"(c[0]), "+f"(c[1]), "+f"(c[2]), "+f"(c[3])
        : "r"(a[0]), "r"(a[1]), "r"(a[2]), "r"(a[3]), "r"(b[0]), "r"(b[1]));
}

__device__ __forceinline__ void ldsm4(uint32_t* d, uint32_t addr) {
    asm volatile("ldmatrix.sync.aligned.m8n8.x4.shared.b16 {%0,%1,%2,%3}, [%4];"
        : "=r"(d[0]), "=r"(d[1]), "=r"(d[2]), "=r"(d[3]) : "r"(addr));
}

// swizzled element offset (in ushorts) for tile [row][16] with 16B-unit swap
__device__ __forceinline__ int swz8(int row, int khalf) {
    return row * 16 + ((khalf ^ ((row >> 2) & 1)) << 3);
}

// stage 8 consecutive values (row, khalf) as one uint4 per tile
#define STAGE_ROW8(HI, LO, off, v0, v1)                                   \
    {   uint32_t hp0,lp0,hp1,lp1,hp2,lp2,hp3,lp3;                         \
        bsplit2((v0).x,(v0).y,hp0,lp0); bsplit2((v0).z,(v0).w,hp1,lp1);   \
        bsplit2((v1).x,(v1).y,hp2,lp2); bsplit2((v1).z,(v1).w,hp3,lp3);   \
        *(uint4*)&(HI)[off] = make_uint4(hp0,hp1,hp2,hp3);                \
        *(uint4*)&(LO)[off] = make_uint4(lp0,lp1,lp2,lp3); }

__device__ __forceinline__ float warpReduceSum(float v) {
    #pragma unroll
    for (int o = 16; o > 0; o >>= 1) v += __shfl_xor_sync(0xffffffffu, v, o);
    return v;
}
__device__ __forceinline__ float warpReduceMax(float v) {
    #pragma unroll
    for (int o = 16; o > 0; o >>= 1) v = fmaxf(v, __shfl_xor_sync(0xffffffffu, v, o));
    return v;
}
__device__ __forceinline__ float blockReduceSum256(float v) {
    __shared__ float sh[33];
    int tid = threadIdx.x, lane = tid & 31, wid = tid >> 5;
    v = warpReduceSum(v);
    if (lane == 0) sh[wid] = v;
    __syncthreads();
    if (tid < 8) {
        float x = sh[tid];
        #pragma unroll
        for (int o = 4; o > 0; o >>= 1) x += __shfl_xor_sync(0xffu, x, o);
        if (tid == 0) sh[32] = x;
    }
    __syncthreads();
    float r = sh[32];
    __syncthreads();
    return r;
}
__device__ __forceinline__ float blockReduceMax256(float v) {
    __shared__ float sh[33];
    int tid = threadIdx.x, lane = tid & 31, wid = tid >> 5;
    v = warpReduceMax(v);
    if (lane == 0) sh[wid] = v;
    __syncthreads();
    if (tid < 8) {
        float x = sh[tid];
        #pragma unroll
        for (int o = 4; o > 0; o >>= 1) x = fmaxf(x, __shfl_xor_sync(0xffu, x, o));
        if (tid == 0) sh[32] = x;
    }
    __syncthreads();
    float r = sh[32];
    __syncthreads();
    return r;
}

// 6 split MMAs for one nj with B frag pair (bh, bl each 2 regs)
#define SPLIT_MMA(ACC0, ACC1, AH, AL, BH, BL)                             \
    mma16(ACC0, AH[0], BH); mma16(ACC1, AH[1], BH);                        \
    mma16(ACC0, AL[0], BH); mma16(ACC1, AL[1], BH);                        \
    mma16(ACC0, AH[0], BL); mma16(ACC1, AH[1], BL);

// =====================  generic bf16x3 MMA GEMM  ============================
// C[M x N] = act(A @ W + bias).  A row-major [M x Kd], W row-major [Kd x N].
// Block tile 128x128, K-step 16, 256 threads (8 warps, 4m x 2n, warp 32x64).
template<int ACT>
__global__ void __launch_bounds__(256)
mma_gemm_kernel(const float* __restrict__ A, const float* __restrict__ W,
                const float* __restrict__ bias, float* __restrict__ C,
                int N, int Kd)
{
    __shared__ unsigned short As_hi[2*2048], As_lo[2*2048];
    __shared__ unsigned short Bs_hi[2*2048], Bs_lo[2*2048];

    const int tid = threadIdx.x, lane = tid & 31, wid = tid >> 5;
    const int g = lane >> 2, tg = lane & 3;
    const int wm = (wid & 3) * 32, wn = (wid >> 2) * 64;
    const int m0 = blockIdx.y * 128, n0 = blockIdx.x * 128;

    const int lm = tid >> 1, lkh = (tid & 1);
    const int bkr = tid >> 4, bnc = (tid & 15) * 4;
    const int aso = swz8(lm, lkh);

    const float* Ap = A + (long long)(m0 + lm) * Kd + lkh * 8;
    const float* Wp = W + (long long)bkr * N + n0 + bnc;

    // ldmatrix lane addresses (byte offsets into tile)
    const int rA = wm + ((lane >> 3) & 1) * 8 + (lane & 7);
    const uint32_t aOff = (uint32_t)(swz8(rA, (lane >> 4) & 1) * 2);
    const int cB = wn + ((lane >> 4) & 1) * 8 + (lane & 7);
    const uint32_t bOff = (uint32_t)(swz8(cB, (lane >> 3) & 1) * 2);
    const uint32_t aHiB = (uint32_t)__cvta_generic_to_shared(As_hi) + aOff;
    const uint32_t aLoB = (uint32_t)__cvta_generic_to_shared(As_lo) + aOff;
    const uint32_t bHiB = (uint32_t)__cvta_generic_to_shared(Bs_hi) + bOff;
    const uint32_t bLoB = (uint32_t)__cvta_generic_to_shared(Bs_lo) + bOff;

    float acc[2][8][4];
    #pragma unroll
    for (int i = 0; i < 2; i++)
        #pragma unroll
        for (int j = 0; j < 8; j++)
            #pragma unroll
            for (int q = 0; q < 4; q++) acc[i][j][q] = 0.f;

    // prologue: stage 0
    {
        float4 a0 = *(const float4*)(Ap);
        float4 a1 = *(const float4*)(Ap + 4);
        STAGE_ROW8(As_hi, As_lo, aso, a0, a1);
        float4 w0 = *(const float4*)(Wp);
        float4 w1 = *(const float4*)(Wp + 64);
        float wv0[4] = {w0.x,w0.y,w0.z,w0.w};
        float wv1[4] = {w1.x,w1.y,w1.z,w1.w};
        #pragma unroll
        for (int i = 0; i < 4; i++) {
            unsigned short h, l;
            int c0 = bnc + i;
            int o0 = swz8(c0, bkr >> 3) + (bkr & 7);
            bsplit(wv0[i], h, l);
            Bs_hi[o0] = h; Bs_lo[o0] = l;
            int c1 = bnc + i + 64;
            int o1 = swz8(c1, bkr >> 3) + (bkr & 7);
            bsplit(wv1[i], h, l);
            Bs_hi[o1] = h; Bs_lo[o1] = l;
        }
    }
    __syncthreads();

    const int nit = Kd / 16;
    for (int it = 0; it < nit; it++) {
        float4 na0, na1, nw0, nw1;
        if (it + 1 < nit) {
            const float* Ap2 = Ap + (it + 1) * 16;
            na0 = *(const float4*)(Ap2);
            na1 = *(const float4*)(Ap2 + 4);
            const float* Wp2 = Wp + (long long)(it + 1) * 16 * N;
            nw0 = *(const float4*)(Wp2);
            nw1 = *(const float4*)(Wp2 + 64);
        }
        const uint32_t st = (uint32_t)(it & 1) * 4096;
        uint32_t ah[2][4], al[2][4];
        ldsm4(ah[0], aHiB + st);        ldsm4(ah[1], aHiB + st + 512);
        ldsm4(al[0], aLoB + st);        ldsm4(al[1], aLoB + st + 512);
        #pragma unroll
        for (int p = 0; p < 4; p++) {
            uint32_t bh[4], bl[4];
            ldsm4(bh, bHiB + st + p * 512);
            ldsm4(bl, bLoB + st + p * 512);
            SPLIT_MMA(acc[0][2*p],   acc[1][2*p],   ah, al, (bh + 0), (bl + 0));
            SPLIT_MMA(acc[0][2*p+1], acc[1][2*p+1], ah, al, (bh + 2), (bl + 2));
        }
        if (it + 1 < nit) {
            const int nx = ((it + 1) & 1) * 2048;
            STAGE_ROW8(As_hi + nx, As_lo + nx, aso, na0, na1);
            float wv0[4] = {nw0.x,nw0.y,nw0.z,nw0.w};
            float wv1[4] = {nw1.x,nw1.y,nw1.z,nw1.w};
            #pragma unroll
            for (int i = 0; i < 4; i++) {
                unsigned short h, l;
                int c0 = bnc + i;
                int o0 = nx + swz8(c0, bkr >> 3) + (bkr & 7);
                bsplit(wv0[i], h, l);
                Bs_hi[o0] = h; Bs_lo[o0] = l;
                int c1 = bnc + i + 64;
                int o1 = nx + swz8(c1, bkr >> 3) + (bkr & 7);
                bsplit(wv1[i], h, l);
                Bs_hi[o1] = h; Bs_lo[o1] = l;
            }
        }
        __syncthreads();
    }

    #pragma unroll
    for (int mi = 0; mi < 2; mi++) {
        const int r0 = m0 + wm + mi * 16 + g;
        #pragma unroll
        for (int nj = 0; nj < 8; nj++) {
            const int c = n0 + wn + nj * 8 + tg * 2;
            const float b0v = bias[c], b1v = bias[c + 1];
            float v0 = acc[mi][nj][0] + b0v, v1 = acc[mi][nj][1] + b1v;
            float v2 = acc[mi][nj][2] + b0v, v3 = acc[mi][nj][3] + b1v;
            if (ACT) { v0 = gelu_tanh(v0); v1 = gelu_tanh(v1); v2 = gelu_tanh(v2); v3 = gelu_tanh(v3); }
            *(float2*)&C[(long long)r0 * N + c]       = make_float2(v0, v1);
            *(float2*)&C[(long long)(r0 + 8) * N + c] = make_float2(v2, v3);
        }
    }
}

// ==================  gathered expert GEMMs (bf16x3 MMA)  ====================
template<int MODE>
__global__ void __launch_bounds__(256)
mma_expert_kernel(const float* __restrict__ Wmat, const float* __restrict__ bias)
{
    const int e = blockIdx.z;
    const int cnt = g_cnt[e];
    const int r0blk = blockIdx.y * 128;
    if (r0blk >= cnt) return;

    const int N  = MODE ? Dm : Fd;
    const int Kd = MODE ? Fd : Dm;

    __shared__ unsigned short As_hi[2*2048], As_lo[2*2048];
    __shared__ unsigned short Bs_hi[2*2048], Bs_lo[2*2048];
    __shared__ int toks[128];

    const int tid = threadIdx.x, lane = tid & 31, wid = tid >> 5;
    const int g = lane >> 2, tg = lane & 3;
    const int wm = (wid & 3) * 32, wn = (wid >> 2) * 64;
    const int n0 = blockIdx.x * 128;

    if (tid < 128) {
        int r = r0blk + tid;
        toks[tid] = (r < cnt) ? g_list[e * Tt + r] : -1;
    }
    __syncthreads();

    const int lm = tid >> 1, lkh = (tid & 1);
    const int bkr = tid >> 4, bnc = (tid & 15) * 4;
    const int aso = swz8(lm, lkh);

    const int entA = toks[lm];
    long long arow;
    const float* Abase;
    if (MODE == 0) { arow = (entA >= 0) ? (long long)(entA >> 1) : 0; Abase = g_x1; }
    else           { arow = (entA >= 0) ? (long long)entA        : 0; Abase = g_eh; }
    const float* Ap = Abase + arow * Kd + lkh * 8;
    const float* Wp = Wmat + (long long)e * Dm * Fd + (long long)bkr * N + n0 + bnc;
    const float* bp = bias + (long long)e * N;

    const int rA = wm + ((lane >> 3) & 1) * 8 + (lane & 7);
    const uint32_t aOff = (uint32_t)(swz8(rA, (lane >> 4) & 1) * 2);
    const int cB = wn + ((lane >> 4) & 1) * 8 + (lane & 7);
    const uint32_t bOff = (uint32_t)(swz8(cB, (lane >> 3) & 1) * 2);
    const uint32_t aHiB = (uint32_t)__cvta_generic_to_shared(As_hi) + aOff;
    const uint32_t aLoB = (uint32_t)__cvta_generic_to_shared(As_lo) + aOff;
    const uint32_t bHiB = (uint32_t)__cvta_generic_to_shared(Bs_hi) + bOff;
    const uint32_t bLoB = (uint32_t)__cvta_generic_to_shared(Bs_lo) + bOff;

    float acc[2][8][4];
    #pragma unroll
    for (int i = 0; i < 2; i++)
        #pragma unroll
        for (int j = 0; j < 8; j++)
            #pragma unroll
            for (int q = 0; q < 4; q++) acc[i][j][q] = 0.f;

    {
        float4 a0 = *(const float4*)(Ap);
        float4 a1 = *(const float4*)(Ap + 4);
        STAGE_ROW8(As_hi, As_lo, aso, a0, a1);
        float4 w0 = *(const float4*)(Wp);
        float4 w1 = *(const float4*)(Wp + 64);
        float wv0[4] = {w0.x,w0.y,w0.z,w0.w};
        float wv1[4] = {w1.x,w1.y,w1.z,w1.w};
        #pragma unroll
        for (int i = 0; i < 4; i++) {
            unsigned short h, l;
            int c0 = bnc + i;
            int o0 = swz8(c0, bkr >> 3) + (bkr & 7);
            bsplit(wv0[i], h, l);
            Bs_hi[o0] = h; Bs_lo[o0] = l;
            int c1 = bnc + i + 64;
            int o1 = swz8(c1, bkr >> 3) + (bkr & 7);
            bsplit(wv1[i], h, l);
            Bs_hi[o1] = h; Bs_lo[o1] = l;
        }
    }
    __syncthreads();

    const int nit = Kd / 16;
    for (int it = 0; it < nit; it++) {
        float4 na0, na1, nw0, nw1;
        if (it + 1 < nit) {
            const float* Ap2 = Ap + (it + 1) * 16;
            na0 = *(const float4*)(Ap2);
            na1 = *(const float4*)(Ap2 + 4);
            const float* Wp2 = Wp + (long long)(it + 1) * 16 * N;
            nw0 = *(const float4*)(Wp2);
            nw1 = *(const float4*)(Wp2 + 64);
        }
        const uint32_t st = (uint32_t)(it & 1) * 4096;
        uint32_t ah[2][4], al[2][4];
        ldsm4(ah[0], aHiB + st);        ldsm4(ah[1], aHiB + st + 512);
        ldsm4(al[0], aLoB + st);        ldsm4(al[1], aLoB + st + 512);
        #pragma unroll
        for (int p = 0; p < 4; p++) {
            uint32_t bh[4], bl[4];
            ldsm4(bh, bHiB + st + p * 512);
            ldsm4(bl, bLoB + st + p * 512);
            SPLIT_MMA(acc[0][2*p],   acc[1][2*p],   ah, al, (bh + 0), (bl + 0));
            SPLIT_MMA(acc[0][2*p+1], acc[1][2*p+1], ah, al, (bh + 2), (bl + 2));
        }
        if (it + 1 < nit) {
            const int nx = ((it + 1) & 1) * 2048;
            STAGE_ROW8(As_hi + nx, As_lo + nx, aso, na0, na1);
            float wv0[4] = {nw0.x,nw0.y,nw0.z,nw0.w};
            float wv1[4] = {nw1.x,nw1.y,nw1.z,nw1.w};
            #pragma unroll
            for (int i = 0; i < 4; i++) {
                unsigned short h, l;
                int c0 = bnc + i;
                int o0 = nx + swz8(c0, bkr >> 3) + (bkr & 7);
                bsplit(wv0[i], h, l);
                Bs_hi[o0] = h; Bs_lo[o0] = l;
                int c1 = bnc + i + 64;
                int o1 = nx + swz8(c1, bkr >> 3) + (bkr & 7);
                bsplit(wv1[i], h, l);
                Bs_hi[o1] = h; Bs_lo[o1] = l;
            }
        }
        __syncthreads();
    }

    float* Cout = MODE ? g_y : g_eh;
    #pragma unroll
    for (int mi = 0; mi < 2; mi++) {
        const int rr0 = wm + mi * 16 + g;
        const int ent0 = toks[rr0], ent1 = toks[rr0 + 8];
        #pragma unroll
        for (int nj = 0; nj < 8; nj++) {
            const int c = wn + nj * 8 + tg * 2;
            const float b0v = bp[n0 + c], b1v = bp[n0 + c + 1];
            if (ent0 >= 0) {
                float v0 = acc[mi][nj][0] + b0v, v1 = acc[mi][nj][1] + b1v;
                if (MODE == 0) { v0 = gelu_tanh(v0); v1 = gelu_tanh(v1); }
                *(float2*)&Cout[(long long)ent0 * N + n0 + c] = make_float2(v0, v1);
            }
            if (ent1 >= 0) {
                float v2 = acc[mi][nj][2] + b0v, v3 = acc[mi][nj][3] + b1v;
                if (MODE == 0) { v2 = gelu_tanh(v2); v3 = gelu_tanh(v3); }
                *(float2*)&Cout[(long long)ent1 * N + n0 + c] = make_float2(v2, v3);
            }
        }
    }
}

// ================  attention scores (bf16x3 MMA): Q K^T / 8  ================
__global__ void __launch_bounds__(256)
mma_scores_kernel(const float* __restrict__ q, const float* __restrict__ k,
                  float* __restrict__ attn)
{
    __shared__ unsigned short As_hi[2*2048], As_lo[2*2048];
    __shared__ unsigned short Bs_hi[2*2048], Bs_lo[2*2048];

    const int tid = threadIdx.x, lane = tid & 31, wid = tid >> 5;
    const int g = lane >> 2, tg = lane & 3;
    const int wm = (wid & 3) * 32, wn = (wid >> 2) * 64;
    const int bh_ = blockIdx.z; const int b = bh_ >> 3, h = bh_ & 7;
    const int i0 = blockIdx.y * 128, j0 = blockIdx.x * 128;

    const int lm = tid >> 1, lkh = (tid & 1);
    const int aso = swz8(lm, lkh);

    const float* Qp = q + (long long)(b * Ls + i0 + lm) * Dm + h * Hd + lkh * 8;
    const float* Kp = k + (long long)(b * Ls + j0 + lm) * Dm + h * Hd + lkh * 8;

    const int rA = wm + ((lane >> 3) & 1) * 8 + (lane & 7);
    const uint32_t aOff = (uint32_t)(swz8(rA, (lane >> 4) & 1) * 2);
    const int cB = wn + ((lane >> 4) & 1) * 8 + (lane & 7);
    const uint32_t bOff = (uint32_t)(swz8(cB, (lane >> 3) & 1) * 2);
    const uint32_t aHiB = (uint32_t)__cvta_generic_to_shared(As_hi) + aOff;
    const uint32_t aLoB = (uint32_t)__cvta_generic_to_shared(As_lo) + aOff;
    const uint32_t bHiB = (uint32_t)__cvta_generic_to_shared(Bs_hi) + bOff;
    const uint32_t bLoB = (uint32_t)__cvta_generic_to_shared(Bs_lo) + bOff;

    float acc[2][8][4];
    #pragma unroll
    for (int i = 0; i < 2; i++)
        #pragma unroll
        for (int j = 0; j < 8; j++)
            #pragma unroll
            for (int q2 = 0; q2 < 4; q2++) acc[i][j][q2] = 0.f;

    {
        float4 a0 = *(const float4*)(Qp);
        float4 a1 = *(const float4*)(Qp + 4);
        STAGE_ROW8(As_hi, As_lo, aso, a0, a1);
        float4 k0 = *(const float4*)(Kp);
        float4 k1 = *(const float4*)(Kp + 4);
        STAGE_ROW8(Bs_hi, Bs_lo, aso, k0, k1);
    }
    __syncthreads();

    const int nit = Hd / 16;      // 4
    for (int it = 0; it < nit; it++) {
        float4 na0, na1, nk0, nk1;
        if (it + 1 < nit) {
            na0 = *(const float4*)(Qp + (it + 1) * 16);
            na1 = *(const float4*)(Qp + (it + 1) * 16 + 4);
            nk0 = *(const float4*)(Kp + (it + 1) * 16);
            nk1 = *(const float4*)(Kp + (it + 1) * 16 + 4);
        }
        const uint32_t st = (uint32_t)(it & 1) * 4096;
        uint32_t ah[2][4], al[2][4];
        ldsm4(ah[0], aHiB + st);        ldsm4(ah[1], aHiB + st + 512);
        ldsm4(al[0], aLoB + st);        ldsm4(al[1], aLoB + st + 512);
        #pragma unroll
        for (int p = 0; p < 4; p++) {
            uint32_t bh2[4], bl2[4];
            ldsm4(bh2, bHiB + st + p * 512);
            ldsm4(bl2, bLoB + st + p * 512);
            SPLIT_MMA(acc[0][2*p],   acc[1][2*p],   ah, al, (bh2 + 0), (bl2 + 0));
            SPLIT_MMA(acc[0][2*p+1], acc[1][2*p+1], ah, al, (bh2 + 2), (bl2 + 2));
        }
        if (it + 1 < nit) {
            const int nx = ((it + 1) & 1) * 2048;
            STAGE_ROW8(As_hi + nx, As_lo + nx, aso, na0, na1);
            STAGE_ROW8(Bs_hi + nx, Bs_lo + nx, aso, nk0, nk1);
        }
        __syncthreads();
    }

    float* O = attn + (long long)bh_ * Ls * Ls;
    #pragma unroll
    for (int mi = 0; mi < 2; mi++) {
        const int r0 = i0 + wm + mi * 16 + g;
        #pragma unroll
        for (int nj = 0; nj < 8; nj++) {
            const int c = j0 + wn + nj * 8 + tg * 2;
            *(float2*)&O[(long long)r0 * Ls + c] =
                make_float2(acc[mi][nj][0] * 0.125f, acc[mi][nj][1] * 0.125f);
            *(float2*)&O[(long long)(r0 + 8) * Ls + c] =
                make_float2(acc[mi][nj][2] * 0.125f, acc[mi][nj][3] * 0.125f);
        }
    }
}

// =====================  P @ V (bf16x3 MMA)  =================================
// grid = (1, L/128, B*H).  Block 128x64, warp 32x32, Kd = L = 2048.
__global__ void __launch_bounds__(256)
mma_attnv_kernel(const float* __restrict__ attn, const float* __restrict__ v,
                 float* __restrict__ ctx)
{
    __shared__ unsigned short As_hi[2*2048], As_lo[2*2048];
    __shared__ unsigned short Bs_hi[2*1024], Bs_lo[2*1024];

    const int tid = threadIdx.x, lane = tid & 31, wid = tid >> 5;
    const int g = lane >> 2, tg = lane & 3;
    const int wm = (wid & 3) * 32, wn = (wid >> 2) * 32;
    const int bh_ = blockIdx.z; const int b = bh_ >> 3, h = bh_ & 7;
    const int i0 = blockIdx.y * 128;

    const int lm = tid >> 1, lkh = (tid & 1);
    const int bkr = tid >> 4, bnc = (tid & 15) * 4;
    const int aso = swz8(lm, lkh);

    const float* Ap = attn + (long long)bh_ * Ls * Ls + (long long)(i0 + lm) * Ls + lkh * 8;
    const float* Vp = v + (long long)(b * Ls + bkr) * Dm + h * Hd + bnc;

    const int rA = wm + ((lane >> 3) & 1) * 8 + (lane & 7);
    const uint32_t aOff = (uint32_t)(swz8(rA, (lane >> 4) & 1) * 2);
    const int cB = wn + ((lane >> 4) & 1) * 8 + (lane & 7);
    const uint32_t bOff = (uint32_t)(swz8(cB, (lane >> 3) & 1) * 2);
    const uint32_t aHiB = (uint32_t)__cvta_generic_to_shared(As_hi) + aOff;
    const uint32_t aLoB = (uint32_t)__cvta_generic_to_shared(As_lo) + aOff;
    const uint32_t bHiB = (uint32_t)__cvta_generic_to_shared(Bs_hi) + bOff;
    const uint32_t bLoB = (uint32_t)__cvta_generic_to_shared(Bs_lo) + bOff;

    float acc[2][4][4];
    #pragma unroll
    for (int i = 0; i < 2; i++)
        #pragma unroll
        for (int j = 0; j < 4; j++)
            #pragma unroll
            for (int q = 0; q < 4; q++) acc[i][j][q] = 0.f;

    {
        float4 a0 = *(const float4*)(Ap);
        float4 a1 = *(const float4*)(Ap + 4);
        STAGE_ROW8(As_hi, As_lo, aso, a0, a1);
        float4 w0 = *(const float4*)(Vp);
        float wv[4] = {w0.x,w0.y,w0.z,w0.w};
        #pragma unroll
        for (int i = 0; i < 4; i++) {
            unsigned short hh, ll;
            int c0 = bnc + i;
            int o0 = swz8(c0, bkr >> 3) + (bkr & 7);
            bsplit(wv[i], hh, ll);
            Bs_hi[o0] = hh; Bs_lo[o0] = ll;
        }
    }
    __syncthreads();

    const int nit = Ls / 16;      // 128
    for (int it = 0; it < nit; it++) {
        float4 na0, na1, nw0;
        if (it + 1 < nit) {
            na0 = *(const float4*)(Ap + (it + 1) * 16);
            na1 = *(const float4*)(Ap + (it + 1) * 16 + 4);
            nw0 = *(const float4*)(Vp + (long long)(it + 1) * 16 * Dm);
        }
        const uint32_t stA = (uint32_t)(it & 1) * 4096;
        const uint32_t stB = (uint32_t)(it & 1) * 2048;
        uint32_t ah[2][4], al[2][4];
        ldsm4(ah[0], aHiB + stA);        ldsm4(ah[1], aHiB + stA + 512);
        ldsm4(al[0], aLoB + stA);        ldsm4(al[1], aLoB + stA + 512);
        #pragma unroll
        for (int p = 0; p < 2; p++) {
            uint32_t bh2[4], bl2[4];
            ldsm4(bh2, bHiB + stB + p * 512);
            ldsm4(bl2, bLoB + stB + p * 512);
            SPLIT_MMA(acc[0][2*p],   acc[1][2*p],   ah, al, (bh2 + 0), (bl2 + 0));
            SPLIT_MMA(acc[0][2*p+1], acc[1][2*p+1], ah, al, (bh2 + 2), (bl2 + 2));
        }
        if (it + 1 < nit) {
            const int nxA = ((it + 1) & 1) * 2048;
            const int nxB = ((it + 1) & 1) * 1024;
            STAGE_ROW8(As_hi + nxA, As_lo + nxA, aso, na0, na1);
            float wv[4] = {nw0.x,nw0.y,nw0.z,nw0.w};
            #pragma unroll
            for (int i = 0; i < 4; i++) {
                unsigned short hh, ll;
                int c0 = bnc + i;
                int o0 = nxB + swz8(c0, bkr >> 3) + (bkr & 7);
                bsplit(wv[i], hh, ll);
                Bs_hi[o0] = hh; Bs_lo[o0] = ll;
            }
        }
        __syncthreads();
    }

    #pragma unroll
    for (int mi = 0; mi < 2; mi++) {
        const int r0 = b * Ls + i0 + wm + mi * 16 + g;
        #pragma unroll
        for (int nj = 0; nj < 4; nj++) {
            const int c = h * Hd + wn + nj * 8 + tg * 2;
            *(float2*)&ctx[(long long)r0 * Dm + c] =
                make_float2(acc[mi][nj][0], acc[mi][nj][1]);
            *(float2*)&ctx[(long long)(r0 + 8) * Dm + c] =
                make_float2(acc[mi][nj][2], acc[mi][nj][3]);
        }
    }
}

// ======================== elementwise / small kernels =======================
__global__ void __launch_bounds__(256)
softmax_kernel(float* __restrict__ attn)
{
    const long long row = blockIdx.x;
    float* p = attn + row * (long long)Ls;
    const int tid = threadIdx.x;
    float v[8];
    float mx = -1e30f;
    #pragma unroll
    for (int i = 0; i < 8; i++) { v[i] = p[tid + i*256]; mx = fmaxf(mx, v[i]); }
    mx = blockReduceMax256(mx);
    float s = 0.f;
    #pragma unroll
    for (int i = 0; i < 8; i++) { v[i] = __expf(v[i] - mx); s += v[i]; }
    s = blockReduceSum256(s);
    float inv = 1.f / s;
    #pragma unroll
    for (int i = 0; i < 8; i++) p[tid + i*256] = v[i] * inv;
}

__global__ void __launch_bounds__(256)
add_ln_kernel(const float* __restrict__ a, const float* __restrict__ b,
              const float* __restrict__ gam, const float* __restrict__ bet,
              float* __restrict__ out)
{
    const int t = blockIdx.x, tid = threadIdx.x;
    float v0 = a[(long long)t*Dm + tid]       + b[(long long)t*Dm + tid];
    float v1 = a[(long long)t*Dm + tid + 256] + b[(long long)t*Dm + tid + 256];
    float s = blockReduceSum256(v0 + v1);
    float mean = s * (1.0f / Dm);
    float d0 = v0 - mean, d1 = v1 - mean;
    float sq = blockReduceSum256(d0*d0 + d1*d1);
    float rstd = rsqrtf(sq * (1.0f / Dm) + 1e-5f);
    out[(long long)t*Dm + tid]       = d0 * rstd * gam[tid]       + bet[tid];
    out[(long long)t*Dm + tid + 256] = d1 * rstd * gam[tid + 256] + bet[tid + 256];
}

__global__ void __launch_bounds__(256)
gate_logits_kernel(const float* __restrict__ gW2, const float* __restrict__ gb2)
{
    const int t = blockIdx.x * 32 + (threadIdx.x >> 3);
    const int e = threadIdx.x & 7;
    const float* row = g_gh + (long long)t * Dm;
    float s = 0.f;
    #pragma unroll 8
    for (int d = 0; d < Dm; d++) s += row[d] * gW2[d*Ee + e];
    g_logits[t*Ee + e] = s + gb2[e];
}

__global__ void init_kernel(float* __restrict__ loss)
{
    if (threadIdx.x < Ee) g_cnt[threadIdx.x] = 0;
    if (threadIdx.x == 0) *loss = 0.0f;
}

__global__ void __launch_bounds__(256)
topk_kernel()
{
    const int t = blockIdx.x * 256 + threadIdx.x;
    if (t >= Tt) return;
    float lg[Ee];
    #pragma unroll
    for (int e = 0; e < Ee; e++) lg[e] = g_logits[t*Ee + e];
    int i1 = 0;
    #pragma unroll
    for (int e = 1; e < Ee; e++) if (lg[e] > lg[i1]) i1 = e;
    int i2 = -1;
    #pragma unroll
    for (int e = 0; e < Ee; e++) if (e != i1 && (i2 < 0 || lg[e] > lg[i2])) i2 = e;
    float mx = lg[i1];
    float s = 0.f;
    #pragma unroll
    for (int e = 0; e < Ee; e++) s += __expf(lg[e] - mx);
    float p1 = __expf(lg[i1] - mx) / s;
    float p2 = __expf(lg[i2] - mx) / s;
    float dn = p1 + p2 + 1e-9f;
    g_wk[2*t + 0] = p1 / dn;
    g_wk[2*t + 1] = p2 / dn;
    int s1 = atomicAdd(&g_cnt[i1], 1); g_list[i1*Tt + s1] = 2*t + 0;
    int s2 = atomicAdd(&g_cnt[i2], 1); g_list[i2*Tt + s2] = 2*t + 1;
}

__global__ void __launch_bounds__(256)
final_ln_kernel(const float* __restrict__ gam, const float* __restrict__ bet,
                float* __restrict__ out)
{
    const int t = blockIdx.x, tid = threadIdx.x;
    const float w0 = g_wk[2*t], w1 = g_wk[2*t + 1];
    float vv[2];
    #pragma unroll
    for (int i = 0; i < 2; i++) {
        int d = tid + i*256;
        float moe = w0 * g_y[(long long)(2*t)   * Dm + d]
                  + w1 * g_y[(long long)(2*t+1) * Dm + d];
        moe = __bfloat162float(__float2bfloat16(moe));
        vv[i] = g_gen[(long long)t*Dm + d] + moe + g_x1[(long long)t*Dm + d];
    }
    float s = blockReduceSum256(vv[0] + vv[1]);
    float mean = s * (1.0f / Dm);
    float d0 = vv[0] - mean, d1 = vv[1] - mean;
    float sq = blockReduceSum256(d0*d0 + d1*d1);
    float rstd = rsqrtf(sq * (1.0f / Dm) + 1e-5f);
    out[(long long)t*Dm + tid]       = d0 * rstd * gam[tid]       + bet[tid];
    out[(long long)t*Dm + tid + 256] = d1 * rstd * gam[tid + 256] + bet[tid + 256];
}

// ------------------------------- launch -------------------------------------
extern "C" void kernel_launch(void* const* d_in, const int* in_sizes, int n_in,
                              void* d_out, int out_size)
{
    const float* x    = (const float*)d_in[0];
    const float* Wq   = (const float*)d_in[1];
    const float* bq   = (const float*)d_in[2];
    const float* Wk   = (const float*)d_in[3];
    const float* bk   = (const float*)d_in[4];
    const float* Wv   = (const float*)d_in[5];
    const float* bv   = (const float*)d_in[6];
    const float* Wo   = (const float*)d_in[7];
    const float* bo   = (const float*)d_in[8];
    const float* ln1g = (const float*)d_in[9];
    const float* ln1b = (const float*)d_in[10];
    const float* gW1  = (const float*)d_in[11];
    const float* gb1  = (const float*)d_in[12];
    const float* gW2  = (const float*)d_in[13];
    const float* gb2  = (const float*)d_in[14];
    const float* eW1  = (const float*)d_in[15];
    const float* eb1  = (const float*)d_in[16];
    const float* eW2  = (const float*)d_in[17];
    const float* eb2  = (const float*)d_in[18];
    const float* geW1 = (const float*)d_in[19];
    const float* geb1 = (const float*)d_in[20];
    const float* geW2 = (const float*)d_in[21];
    const float* geb2 = (const float*)d_in[22];
    const float* ln2g = (const float*)d_in[23];
    const float* ln2b = (const float*)d_in[24];

    float* out  = (float*)d_out;
    float* attn = out + ATTN_OFF;
    float* loss = out + LOSS_OFF;

    float *pq, *pk, *pv, *pctx, *ptmp, *px1, *pgh, *pgenh, *pgen;
    cudaGetSymbolAddress((void**)&pq,    g_q);
    cudaGetSymbolAddress((void**)&pk,    g_k);
    cudaGetSymbolAddress((void**)&pv,    g_v);
    cudaGetSymbolAddress((void**)&pctx,  g_ctx);
    cudaGetSymbolAddress((void**)&ptmp,  g_tmp);
    cudaGetSymbolAddress((void**)&px1,   g_x1);
    cudaGetSymbolAddress((void**)&pgh,   g_gh);
    cudaGetSymbolAddress((void**)&pgenh, g_genh);
    cudaGetSymbolAddress((void**)&pgen,  g_gen);

    dim3 blk(256);

    // QKV projections (M=4096, N=512, K=512)
    mma_gemm_kernel<0><<<dim3(Dm/128, Tt/128), blk>>>(x, Wq, bq, pq, Dm, Dm);
    mma_gemm_kernel<0><<<dim3(Dm/128, Tt/128), blk>>>(x, Wk, bk, pk, Dm, Dm);
    mma_gemm_kernel<0><<<dim3(Dm/128, Tt/128), blk>>>(x, Wv, bv, pv, Dm, Dm);

    // attention
    mma_scores_kernel<<<dim3(Ls/128, Ls/128, Bb*Hh), blk>>>(pq, pk, attn);
    softmax_kernel<<<Bb*Hh*Ls, blk>>>(attn);
    mma_attnv_kernel<<<dim3(1, Ls/128, Bb*Hh), blk>>>(attn, pv, pctx);
    mma_gemm_kernel<0><<<dim3(Dm/128, Tt/128), blk>>>(pctx, Wo, bo, ptmp, Dm, Dm);
    add_ln_kernel<<<Tt, blk>>>(x, ptmp, ln1g, ln1b, px1);

    // gate
    mma_gemm_kernel<1><<<dim3(Dm/128, Tt/128), blk>>>(px1, gW1, gb1, pgh, Dm, Dm);
    gate_logits_kernel<<<Tt/32, blk>>>(gW2, gb2);
    init_kernel<<<1, 32>>>(loss);
    topk_kernel<<<Tt/256, blk>>>();

    // routed experts (sparse top-2 gather)
    mma_expert_kernel<0><<<dim3(Fd/128, Tt/128, Ee), blk>>>(eW1, eb1);
    mma_expert_kernel<1><<<dim3(Dm/128, Tt/128, Ee), blk>>>(eW2, eb2);

    // general expert
    mma_gemm_kernel<1><<<dim3(Fd/128, Tt/128), blk>>>(px1, geW1, geb1, pgenh, Fd, Dm);
    mma_gemm_kernel<0><<<dim3(Dm/128, Tt/128), blk>>>(pgenh, geW2, geb2, pgen, Dm, Fd);

    // combine + LN2 -> out
    final_ln_kernel<<<Tt, blk>>>(ln2g, ln2b, out);
}

// round 8
// speedup vs baseline: 2.4867x; 1.3388x over previous
#include <cuda_runtime.h>
#include <cuda_bf16.h>
#include <cstdint>

// ---------------------------------------------------------------------------
// MoEEncoderLayer: B=2 L=2048 D=512 H=8 E=8 K=2 DF=2048
// Output layout in d_out (float32): [out: T*D][attn: B*H*L*L][aug_loss: 1]
// bf16x3 split-precision mma.sync m16n8k16; all operands pre-split into
// bf16 hi/lo planes; GEMM mainloop = cp.async + ldmatrix + mma only.
// Fixes: empty commit_group in pipeline tail; attnv B-copies guarded so
// non-owning threads don't zero-fill aliased smem slots.
// ---------------------------------------------------------------------------

#define Bb 2
#define Ls 2048
#define Dm 512
#define Hh 8
#define Ee 8
#define KTOP 2
#define Fd 2048
#define Hd 64
#define Tt (Bb*Ls)                      // 4096
#define NS 4                            // pipeline stages

static const long long ATTN_OFF = (long long)Tt * Dm;                      // 2097152
static const long long LOSS_OFF = ATTN_OFF + (long long)Bb*Hh*Ls*Ls;       // 69206016

// ------------------------- scratch (device globals) ------------------------
__device__ float g_v[Tt*Dm];
__device__ float g_tmp[Tt*Dm];
__device__ float g_x1[Tt*Dm];
__device__ float g_gh[Tt*Dm];
__device__ float g_logits[Tt*Ee];
__device__ float g_wk[Tt*KTOP];
__device__ int   g_cnt[Ee];
__device__ int   g_list[Ee*Tt];
__device__ float g_y[Tt*KTOP*Dm];
__device__ float g_gen[Tt*Dm];

// split planes (bf16 bits as ushort)
__device__ unsigned short s_xh[Tt*Dm],   s_xl[Tt*Dm];
__device__ unsigned short s_qh[Tt*Dm],   s_ql[Tt*Dm];
__device__ unsigned short s_kh[Tt*Dm],   s_kl[Tt*Dm];
__device__ unsigned short s_vth[Tt*Dm],  s_vtl[Tt*Dm];     // vT [Bb][Dm][Ls]
__device__ unsigned short s_ctxh[Tt*Dm], s_ctxl[Tt*Dm];
__device__ unsigned short s_x1h[Tt*Dm],  s_x1l[Tt*Dm];
__device__ unsigned short s_ehh[Tt*KTOP*Fd], s_ehl[Tt*KTOP*Fd];
__device__ unsigned short s_gnh[Tt*Fd],  s_gnl[Tt*Fd];
__device__ unsigned short s_ph[(long long)Bb*Hh*Ls*Ls];
__device__ unsigned short s_pl[(long long)Bb*Hh*Ls*Ls];
// weight planes, transposed to [N x K]
__device__ unsigned short s_wqh[Dm*Dm], s_wql[Dm*Dm];
__device__ unsigned short s_wkh[Dm*Dm], s_wkl[Dm*Dm];
__device__ unsigned short s_wvh[Dm*Dm], s_wvl[Dm*Dm];
__device__ unsigned short s_woh[Dm*Dm], s_wol[Dm*Dm];
__device__ unsigned short s_gw1h[Dm*Dm], s_gw1l[Dm*Dm];
__device__ unsigned short s_gew1h[Fd*Dm], s_gew1l[Fd*Dm];
__device__ unsigned short s_gew2h[Dm*Fd], s_gew2l[Dm*Fd];
__device__ unsigned short s_ew1h[Ee*Fd*Dm], s_ew1l[Ee*Fd*Dm];
__device__ unsigned short s_ew2h[Ee*Dm*Fd], s_ew2l[Ee*Dm*Fd];

// ------------------------------- helpers -----------------------------------
__device__ __forceinline__ float gelu_tanh(float x) {
    float x3 = x * x * x;
    float t  = tanhf(0.7978845608028654f * (x + 0.044715f * x3));
    return 0.5f * x * (1.0f + t);
}
__device__ __forceinline__ void bsplit(float x, unsigned short& h, unsigned short& l) {
    __nv_bfloat16 hb = __float2bfloat16_rn(x);
    float hf = __bfloat162float(hb);
    __nv_bfloat16 lb = __float2bfloat16_rn(x - hf);
    h = __bfloat16_as_ushort(hb);
    l = __bfloat16_as_ushort(lb);
}
__device__ __forceinline__ void bsplit2(float x0, float x1, uint32_t& hp, uint32_t& lp) {
    unsigned short h0, l0, h1, l1;
    bsplit(x0, h0, l0);
    bsplit(x1, h1, l1);
    hp = (uint32_t)h0 | ((uint32_t)h1 << 16);
    lp = (uint32_t)l0 | ((uint32_t)l1 << 16);
}
__device__ __forceinline__ void mma16(float* c, const uint32_t* a, const uint32_t* b) {
    asm volatile(
        "mma.sync.aligned.m16n8k16.row.col.f32.bf16.bf16.f32 "
        "{%0,%1,%2,%3}, {%4,%5,%6,%7}, {%8,%9}, {%0,%1,%2,%3};"
        : "+f"(c[0]), "+f"(c[1]), "+f"(c[2]), "+f"(c[3])
        : "r"(a[0]), "r"(a[1]), "r"(a[2]), "r"(a[3]), "r"(b[0]), "r"(b[1]));
}
__device__ __forceinline__ void ldsm4(uint32_t* d, uint32_t addr) {
    asm volatile("ldmatrix.sync.aligned.m8n8.x4.shared.b16 {%0,%1,%2,%3}, [%4];"
        : "=r"(d[0]), "=r"(d[1]), "=r"(d[2]), "=r"(d[3]) : "r"(addr));
}
__device__ __forceinline__ void cpa16(uint32_t dst, const void* src, bool pred) {
    int sz = pred ? 16 : 0;
    asm volatile("cp.async.cg.shared.global [%0], [%1], 16, %2;\n"
        :: "r"(dst), "l"(src), "r"(sz));
}
__device__ __forceinline__ void cpa_commit() { asm volatile("cp.async.commit_group;"); }
template<int N> __device__ __forceinline__ void cpa_wait() {
    asm volatile("cp.async.wait_group %0;" :: "n"(N));
}
__device__ __forceinline__ int swz8(int row, int khalf) {
    return row * 16 + ((khalf ^ ((row >> 2) & 1)) << 3);
}

__device__ __forceinline__ float warpReduceSum(float v) {
    #pragma unroll
    for (int o = 16; o > 0; o >>= 1) v += __shfl_xor_sync(0xffffffffu, v, o);
    return v;
}
__device__ __forceinline__ float warpReduceMax(float v) {
    #pragma unroll
    for (int o = 16; o > 0; o >>= 1) v = fmaxf(v, __shfl_xor_sync(0xffffffffu, v, o));
    return v;
}
__device__ __forceinline__ float blockReduceSum256(float v) {
    __shared__ float sh[33];
    int tid = threadIdx.x, lane = tid & 31, wid = tid >> 5;
    v = warpReduceSum(v);
    if (lane == 0) sh[wid] = v;
    __syncthreads();
    if (tid < 8) {
        float x = sh[tid];
        #pragma unroll
        for (int o = 4; o > 0; o >>= 1) x += __shfl_xor_sync(0xffu, x, o);
        if (tid == 0) sh[32] = x;
    }
    __syncthreads();
    float r = sh[32];
    __syncthreads();
    return r;
}
__device__ __forceinline__ float blockReduceMax256(float v) {
    __shared__ float sh[33];
    int tid = threadIdx.x, lane = tid & 31, wid = tid >> 5;
    v = warpReduceMax(v);
    if (lane == 0) sh[wid] = v;
    __syncthreads();
    if (tid < 8) {
        float x = sh[tid];
        #pragma unroll
        for (int o = 4; o > 0; o >>= 1) x = fmaxf(x, __shfl_xor_sync(0xffu, x, o));
        if (tid == 0) sh[32] = x;
    }
    __syncthreads();
    float r = sh[32];
    __syncthreads();
    return r;
}

#define SPLIT_MMA(ACC0, ACC1, AH, AL, BH, BL)                             \
    mma16(ACC0, AH[0], BH); mma16(ACC1, AH[1], BH);                        \
    mma16(ACC0, AL[0], BH); mma16(ACC1, AL[1], BH);                        \
    mma16(ACC0, AH[0], BL); mma16(ACC1, AH[1], BL);

// ======================= conversion kernels ================================
__global__ void __launch_bounds__(256)
esplit_kernel(const float* __restrict__ in, unsigned short* __restrict__ oh,
              unsigned short* __restrict__ ol, int n)
{
    int i = blockIdx.x * 256 + threadIdx.x;
    if (i < n) {
        unsigned short h, l;
        bsplit(in[i], h, l);
        oh[i] = h; ol[i] = l;
    }
}

// in [K x N] fp32 (batched) -> planes [N x K] bf16 hi/lo (batched)
__global__ void __launch_bounds__(256)
wsplit_t_kernel(const float* __restrict__ in, unsigned short* __restrict__ oh,
                unsigned short* __restrict__ ol, int K, int N)
{
    __shared__ float t[32][33];
    long long base = (long long)blockIdx.z * K * N;
    int n0 = blockIdx.x * 32, k0 = blockIdx.y * 32;
    int tx = threadIdx.x & 31, ty = threadIdx.x >> 5;   // (32, 8)
    #pragma unroll
    for (int i = 0; i < 4; i++)
        t[ty + i*8][tx] = in[base + (long long)(k0 + ty + i*8) * N + n0 + tx];
    __syncthreads();
    #pragma unroll
    for (int i = 0; i < 4; i++) {
        unsigned short h, l;
        bsplit(t[tx][ty + i*8], h, l);
        long long o = base + (long long)(n0 + ty + i*8) * K + k0 + tx;
        oh[o] = h; ol[o] = l;
    }
}

// ===================== generic GEMM (pre-split planes) ======================
// C = act(A @ W + bias); A planes [M x Kd]; B planes [N x Kd] (pre-transposed)
// OMODE: 0 = fp32 C, 1 = split planes C, 2 = both
template<int ACT, int OMODE>
__global__ void __launch_bounds__(256)
gemm_s(const unsigned short* __restrict__ Ahi, const unsigned short* __restrict__ Alo,
       const unsigned short* __restrict__ Bhi, const unsigned short* __restrict__ Blo,
       const float* __restrict__ bias, float* __restrict__ Cf,
       unsigned short* __restrict__ Chi, unsigned short* __restrict__ Clo,
       int N, int Kd)
{
    extern __shared__ unsigned short sm[];
    unsigned short* As_hi = sm;
    unsigned short* As_lo = sm + NS*2048;
    unsigned short* Bs_hi = sm + 2*NS*2048;
    unsigned short* Bs_lo = sm + 3*NS*2048;

    const int tid = threadIdx.x, lane = tid & 31, wid = tid >> 5;
    const int g = lane >> 2, tg = lane & 3;
    const int wm = (wid & 3) * 32, wn = (wid >> 2) * 64;
    const int m0 = blockIdx.y * 128, n0 = blockIdx.x * 128;

    const int lm = tid >> 1, lkh = tid & 1;
    const int aso = swz8(lm, lkh);

    const unsigned short* Ah = Ahi + (long long)(m0 + lm) * Kd + lkh * 8;
    const unsigned short* Al = Alo + (long long)(m0 + lm) * Kd + lkh * 8;
    const unsigned short* Bh = Bhi + (long long)(n0 + lm) * Kd + lkh * 8;
    const unsigned short* Bl = Blo + (long long)(n0 + lm) * Kd + lkh * 8;

    const uint32_t aHiS = (uint32_t)__cvta_generic_to_shared(As_hi) + aso*2;
    const uint32_t aLoS = (uint32_t)__cvta_generic_to_shared(As_lo) + aso*2;
    const uint32_t bHiS = (uint32_t)__cvta_generic_to_shared(Bs_hi) + aso*2;
    const uint32_t bLoS = (uint32_t)__cvta_generic_to_shared(Bs_lo) + aso*2;

    const int rA = wm + ((lane >> 3) & 1) * 8 + (lane & 7);
    const uint32_t aOff = (uint32_t)(swz8(rA, (lane >> 4) & 1) * 2);
    const int cB = wn + ((lane >> 4) & 1) * 8 + (lane & 7);
    const uint32_t bOff = (uint32_t)(swz8(cB, (lane >> 3) & 1) * 2);
    const uint32_t aHiB = (uint32_t)__cvta_generic_to_shared(As_hi) + aOff;
    const uint32_t aLoB = (uint32_t)__cvta_generic_to_shared(As_lo) + aOff;
    const uint32_t bHiB = (uint32_t)__cvta_generic_to_shared(Bs_hi) + bOff;
    const uint32_t bLoB = (uint32_t)__cvta_generic_to_shared(Bs_lo) + bOff;

    float acc[2][8][4];
    #pragma unroll
    for (int i = 0; i < 2; i++)
        #pragma unroll
        for (int j = 0; j < 8; j++)
            #pragma unroll
            for (int q = 0; q < 4; q++) acc[i][j][q] = 0.f;

    const int nit = Kd / 16;
    #define G_ISSUE(s, k0v) { uint32_t o = (uint32_t)(s)*4096;              \
        cpa16(aHiS + o, Ah + (k0v), true); cpa16(aLoS + o, Al + (k0v), true);\
        cpa16(bHiS + o, Bh + (k0v), true); cpa16(bLoS + o, Bl + (k0v), true);\
        cpa_commit(); }

    #pragma unroll
    for (int s = 0; s < NS-1; s++) if (s < nit) G_ISSUE(s, s*16);

    for (int it = 0; it < nit; it++) {
        cpa_wait<NS-2>();
        __syncthreads();
        const uint32_t st = (uint32_t)(it & (NS-1)) * 4096;
        uint32_t ah[2][4], al[2][4];
        ldsm4(ah[0], aHiB + st);  ldsm4(ah[1], aHiB + st + 512);
        ldsm4(al[0], aLoB + st);  ldsm4(al[1], aLoB + st + 512);
        #pragma unroll
        for (int p = 0; p < 4; p++) {
            uint32_t bh[4], bl[4];
            ldsm4(bh, bHiB + st + p * 512);
            ldsm4(bl, bLoB + st + p * 512);
            SPLIT_MMA(acc[0][2*p],   acc[1][2*p],   ah, al, (bh + 0), (bl + 0));
            SPLIT_MMA(acc[0][2*p+1], acc[1][2*p+1], ah, al, (bh + 2), (bl + 2));
        }
        int nxt = it + NS - 1;
        if (nxt < nit) { G_ISSUE(nxt & (NS-1), nxt*16); } else { cpa_commit(); }
    }
    #undef G_ISSUE

    #pragma unroll
    for (int mi = 0; mi < 2; mi++) {
        const int r0 = m0 + wm + mi * 16 + g;
        #pragma unroll
        for (int nj = 0; nj < 8; nj++) {
            const int c = n0 + wn + nj * 8 + tg * 2;
            const float b0v = bias[c], b1v = bias[c + 1];
            float v0 = acc[mi][nj][0] + b0v, v1 = acc[mi][nj][1] + b1v;
            float v2 = acc[mi][nj][2] + b0v, v3 = acc[mi][nj][3] + b1v;
            if (ACT) { v0 = gelu_tanh(v0); v1 = gelu_tanh(v1); v2 = gelu_tanh(v2); v3 = gelu_tanh(v3); }
            if (OMODE == 0 || OMODE == 2) {
                *(float2*)&Cf[(long long)r0 * N + c]       = make_float2(v0, v1);
                *(float2*)&Cf[(long long)(r0 + 8) * N + c] = make_float2(v2, v3);
            }
            if (OMODE >= 1) {
                uint32_t hp, lp;
                bsplit2(v0, v1, hp, lp);
                *(uint32_t*)&Chi[(long long)r0 * N + c] = hp;
                *(uint32_t*)&Clo[(long long)r0 * N + c] = lp;
                bsplit2(v2, v3, hp, lp);
                *(uint32_t*)&Chi[(long long)(r0 + 8) * N + c] = hp;
                *(uint32_t*)&Clo[(long long)(r0 + 8) * N + c] = lp;
            }
        }
    }
}

// ==================  gathered expert GEMMs  =================================
// MODE 0: eh[ent] = gelu(x1[ent>>1] @ eW1[e] + eb1[e])   (N=Fd, Kd=Dm)
// MODE 1: y[ent]  = eh[ent] @ eW2[e] + eb2[e]            (N=Dm, Kd=Fd)
template<int MODE>
__global__ void __launch_bounds__(256)
expert_s(const unsigned short* __restrict__ Whi, const unsigned short* __restrict__ Wlo,
         const float* __restrict__ bias)
{
    const int e = blockIdx.z;
    const int cnt = g_cnt[e];
    const int r0blk = blockIdx.y * 128;
    if (r0blk >= cnt) return;

    const int N  = MODE ? Dm : Fd;
    const int Kd = MODE ? Fd : Dm;

    extern __shared__ unsigned short sm[];
    unsigned short* As_hi = sm;
    unsigned short* As_lo = sm + NS*2048;
    unsigned short* Bs_hi = sm + 2*NS*2048;
    unsigned short* Bs_lo = sm + 3*NS*2048;
    __shared__ int toks[128];

    const int tid = threadIdx.x, lane = tid & 31, wid = tid >> 5;
    const int g = lane >> 2, tg = lane & 3;
    const int wm = (wid & 3) * 32, wn = (wid >> 2) * 64;
    const int n0 = blockIdx.x * 128;

    if (tid < 128) {
        int r = r0blk + tid;
        toks[tid] = (r < cnt) ? g_list[e * Tt + r] : -1;
    }
    __syncthreads();

    const int lm = tid >> 1, lkh = tid & 1;
    const int aso = swz8(lm, lkh);

    const int entA = toks[lm];
    const bool apred = (entA >= 0);
    long long arow = apred ? (MODE ? (long long)entA : (long long)(entA >> 1)) : 0;
    const unsigned short* Ahp = (MODE ? s_ehh : s_x1h) + arow * Kd + lkh * 8;
    const unsigned short* Alp = (MODE ? s_ehl : s_x1l) + arow * Kd + lkh * 8;
    const unsigned short* Bhp = Whi + (long long)e * Dm * Fd + (long long)(n0 + lm) * Kd + lkh * 8;
    const unsigned short* Blp = Wlo + (long long)e * Dm * Fd + (long long)(n0 + lm) * Kd + lkh * 8;
    const float* bp = bias + (long long)e * N;

    const uint32_t aHiS = (uint32_t)__cvta_generic_to_shared(As_hi) + aso*2;
    const uint32_t aLoS = (uint32_t)__cvta_generic_to_shared(As_lo) + aso*2;
    const uint32_t bHiS = (uint32_t)__cvta_generic_to_shared(Bs_hi) + aso*2;
    const uint32_t bLoS = (uint32_t)__cvta_generic_to_shared(Bs_lo) + aso*2;

    const int rA = wm + ((lane >> 3) & 1) * 8 + (lane & 7);
    const uint32_t aOff = (uint32_t)(swz8(rA, (lane >> 4) & 1) * 2);
    const int cB = wn + ((lane >> 4) & 1) * 8 + (lane & 7);
    const uint32_t bOff = (uint32_t)(swz8(cB, (lane >> 3) & 1) * 2);
    const uint32_t aHiB = (uint32_t)__cvta_generic_to_shared(As_hi) + aOff;
    const uint32_t aLoB = (uint32_t)__cvta_generic_to_shared(As_lo) + aOff;
    const uint32_t bHiB = (uint32_t)__cvta_generic_to_shared(Bs_hi) + bOff;
    const uint32_t bLoB = (uint32_t)__cvta_generic_to_shared(Bs_lo) + bOff;

    float acc[2][8][4];
    #pragma unroll
    for (int i = 0; i < 2; i++)
        #pragma unroll
        for (int j = 0; j < 8; j++)
            #pragma unroll
            for (int q = 0; q < 4; q++) acc[i][j][q] = 0.f;

    const int nit = Kd / 16;
    #define E_ISSUE(s, k0v) { uint32_t o = (uint32_t)(s)*4096;                 \
        cpa16(aHiS + o, Ahp + (k0v), apred); cpa16(aLoS + o, Alp + (k0v), apred);\
        cpa16(bHiS + o, Bhp + (k0v), true);  cpa16(bLoS + o, Blp + (k0v), true); \
        cpa_commit(); }

    #pragma unroll
    for (int s = 0; s < NS-1; s++) if (s < nit) E_ISSUE(s, s*16);

    for (int it = 0; it < nit; it++) {
        cpa_wait<NS-2>();
        __syncthreads();
        const uint32_t st = (uint32_t)(it & (NS-1)) * 4096;
        uint32_t ah[2][4], al[2][4];
        ldsm4(ah[0], aHiB + st);  ldsm4(ah[1], aHiB + st + 512);
        ldsm4(al[0], aLoB + st);  ldsm4(al[1], aLoB + st + 512);
        #pragma unroll
        for (int p = 0; p < 4; p++) {
            uint32_t bh[4], bl[4];
            ldsm4(bh, bHiB + st + p * 512);
            ldsm4(bl, bLoB + st + p * 512);
            SPLIT_MMA(acc[0][2*p],   acc[1][2*p],   ah, al, (bh + 0), (bl + 0));
            SPLIT_MMA(acc[0][2*p+1], acc[1][2*p+1], ah, al, (bh + 2), (bl + 2));
        }
        int nxt = it + NS - 1;
        if (nxt < nit) { E_ISSUE(nxt & (NS-1), nxt*16); } else { cpa_commit(); }
    }
    #undef E_ISSUE

    #pragma unroll
    for (int mi = 0; mi < 2; mi++) {
        const int rr0 = wm + mi * 16 + g;
        const int ent0 = toks[rr0], ent1 = toks[rr0 + 8];
        #pragma unroll
        for (int nj = 0; nj < 8; nj++) {
            const int c = wn + nj * 8 + tg * 2;
            const float b0v = bp[n0 + c], b1v = bp[n0 + c + 1];
            if (ent0 >= 0) {
                float v0 = acc[mi][nj][0] + b0v, v1 = acc[mi][nj][1] + b1v;
                if (MODE == 0) {
                    v0 = gelu_tanh(v0); v1 = gelu_tanh(v1);
                    uint32_t hp, lp;
                    bsplit2(v0, v1, hp, lp);
                    *(uint32_t*)&s_ehh[(long long)ent0 * Fd + n0 + c] = hp;
                    *(uint32_t*)&s_ehl[(long long)ent0 * Fd + n0 + c] = lp;
                } else {
                    *(float2*)&g_y[(long long)ent0 * Dm + n0 + c] = make_float2(v0, v1);
                }
            }
            if (ent1 >= 0) {
                float v2 = acc[mi][nj][2] + b0v, v3 = acc[mi][nj][3] + b1v;
                if (MODE == 0) {
                    v2 = gelu_tanh(v2); v3 = gelu_tanh(v3);
                    uint32_t hp, lp;
                    bsplit2(v2, v3, hp, lp);
                    *(uint32_t*)&s_ehh[(long long)ent1 * Fd + n0 + c] = hp;
                    *(uint32_t*)&s_ehl[(long long)ent1 * Fd + n0 + c] = lp;
                } else {
                    *(float2*)&g_y[(long long)ent1 * Dm + n0 + c] = make_float2(v2, v3);
                }
            }
        }
    }
}

// ================  attention scores: Q K^T / 8  =============================
__global__ void __launch_bounds__(256)
scores_s(float* __restrict__ attn)
{
    extern __shared__ unsigned short sm[];
    unsigned short* As_hi = sm;
    unsigned short* As_lo = sm + NS*2048;
    unsigned short* Bs_hi = sm + 2*NS*2048;
    unsigned short* Bs_lo = sm + 3*NS*2048;

    const int tid = threadIdx.x, lane = tid & 31, wid = tid >> 5;
    const int g = lane >> 2, tg = lane & 3;
    const int wm = (wid & 3) * 32, wn = (wid >> 2) * 64;
    const int bh_ = blockIdx.z; const int b = bh_ >> 3, h = bh_ & 7;
    const int i0 = blockIdx.y * 128, j0 = blockIdx.x * 128;

    const int lm = tid >> 1, lkh = tid & 1;
    const int aso = swz8(lm, lkh);

    const unsigned short* Ah = s_qh + (long long)(b*Ls + i0 + lm) * Dm + h*Hd + lkh*8;
    const unsigned short* Al = s_ql + (long long)(b*Ls + i0 + lm) * Dm + h*Hd + lkh*8;
    const unsigned short* Bh = s_kh + (long long)(b*Ls + j0 + lm) * Dm + h*Hd + lkh*8;
    const unsigned short* Bl = s_kl + (long long)(b*Ls + j0 + lm) * Dm + h*Hd + lkh*8;

    const uint32_t aHiS = (uint32_t)__cvta_generic_to_shared(As_hi) + aso*2;
    const uint32_t aLoS = (uint32_t)__cvta_generic_to_shared(As_lo) + aso*2;
    const uint32_t bHiS = (uint32_t)__cvta_generic_to_shared(Bs_hi) + aso*2;
    const uint32_t bLoS = (uint32_t)__cvta_generic_to_shared(Bs_lo) + aso*2;

    const int rA = wm + ((lane >> 3) & 1) * 8 + (lane & 7);
    const uint32_t aOff = (uint32_t)(swz8(rA, (lane >> 4) & 1) * 2);
    const int cB = wn + ((lane >> 4) & 1) * 8 + (lane & 7);
    const uint32_t bOff = (uint32_t)(swz8(cB, (lane >> 3) & 1) * 2);
    const uint32_t aHiB = (uint32_t)__cvta_generic_to_shared(As_hi) + aOff;
    const uint32_t aLoB = (uint32_t)__cvta_generic_to_shared(As_lo) + aOff;
    const uint32_t bHiB = (uint32_t)__cvta_generic_to_shared(Bs_hi) + bOff;
    const uint32_t bLoB = (uint32_t)__cvta_generic_to_shared(Bs_lo) + bOff;

    float acc[2][8][4];
    #pragma unroll
    for (int i = 0; i < 2; i++)
        #pragma unroll
        for (int j = 0; j < 8; j++)
            #pragma unroll
            for (int q2 = 0; q2 < 4; q2++) acc[i][j][q2] = 0.f;

    const int nit = Hd / 16;   // 4
    #define S_ISSUE(s, k0v) { uint32_t o = (uint32_t)(s)*4096;              \
        cpa16(aHiS + o, Ah + (k0v), true); cpa16(aLoS + o, Al + (k0v), true);\
        cpa16(bHiS + o, Bh + (k0v), true); cpa16(bLoS + o, Bl + (k0v), true);\
        cpa_commit(); }

    #pragma unroll
    for (int s = 0; s < NS-1; s++) if (s < nit) S_ISSUE(s, s*16);

    for (int it = 0; it < nit; it++) {
        cpa_wait<NS-2>();
        __syncthreads();
        const uint32_t st = (uint32_t)(it & (NS-1)) * 4096;
        uint32_t ah[2][4], al[2][4];
        ldsm4(ah[0], aHiB + st);  ldsm4(ah[1], aHiB + st + 512);
        ldsm4(al[0], aLoB + st);  ldsm4(al[1], aLoB + st + 512);
        #pragma unroll
        for (int p = 0; p < 4; p++) {
            uint32_t bh2[4], bl2[4];
            ldsm4(bh2, bHiB + st + p * 512);
            ldsm4(bl2, bLoB + st + p * 512);
            SPLIT_MMA(acc[0][2*p],   acc[1][2*p],   ah, al, (bh2 + 0), (bl2 + 0));
            SPLIT_MMA(acc[0][2*p+1], acc[1][2*p+1], ah, al, (bh2 + 2), (bl2 + 2));
        }
        int nxt = it + NS - 1;
        if (nxt < nit) { S_ISSUE(nxt & (NS-1), nxt*16); } else { cpa_commit(); }
    }
    #undef S_ISSUE

    float* O = attn + (long long)bh_ * Ls * Ls;
    #pragma unroll
    for (int mi = 0; mi < 2; mi++) {
        const int r0 = i0 + wm + mi * 16 + g;
        #pragma unroll
        for (int nj = 0; nj < 8; nj++) {
            const int c = j0 + wn + nj * 8 + tg * 2;
            *(float2*)&O[(long long)r0 * Ls + c] =
                make_float2(acc[mi][nj][0] * 0.125f, acc[mi][nj][1] * 0.125f);
            *(float2*)&O[(long long)(r0 + 8) * Ls + c] =
                make_float2(acc[mi][nj][2] * 0.125f, acc[mi][nj][3] * 0.125f);
        }
    }
}

// =====================  P @ V  ==============================================
// grid = (1, L/128, B*H).  Block 128x64, warp 32x32, Kd = L = 2048.
__global__ void __launch_bounds__(256)
attnv_s()
{
    extern __shared__ unsigned short sm[];
    unsigned short* As_hi = sm;                 // NS*2048
    unsigned short* As_lo = sm + NS*2048;
    unsigned short* Bs_hi = sm + 2*NS*2048;     // NS*1024
    unsigned short* Bs_lo = sm + 2*NS*2048 + NS*1024;

    const int tid = threadIdx.x, lane = tid & 31, wid = tid >> 5;
    const int g = lane >> 2, tg = lane & 3;
    const int wm = (wid & 3) * 32, wn = (wid >> 2) * 32;
    const int bh_ = blockIdx.z; const int b = bh_ >> 3, h = bh_ & 7;
    const int i0 = blockIdx.y * 128;

    const int lm = tid >> 1, lkh = tid & 1;
    const int aso = swz8(lm, lkh);
    const int blm = lm & 63;
    const bool bpred = tid < 128;
    const int bso = swz8(blm, lkh);

    const unsigned short* Ah = s_ph + (long long)bh_ * Ls * Ls + (long long)(i0 + lm) * Ls + lkh*8;
    const unsigned short* Al = s_pl + (long long)bh_ * Ls * Ls + (long long)(i0 + lm) * Ls + lkh*8;
    const unsigned short* Bh = s_vth + ((long long)b * Dm + h * Hd + blm) * Ls + lkh*8;
    const unsigned short* Bl = s_vtl + ((long long)b * Dm + h * Hd + blm) * Ls + lkh*8;

    const uint32_t aHiS = (uint32_t)__cvta_generic_to_shared(As_hi) + aso*2;
    const uint32_t aLoS = (uint32_t)__cvta_generic_to_shared(As_lo) + aso*2;
    const uint32_t bHiS = (uint32_t)__cvta_generic_to_shared(Bs_hi) + bso*2;
    const uint32_t bLoS = (uint32_t)__cvta_generic_to_shared(Bs_lo) + bso*2;

    const int rA = wm + ((lane >> 3) & 1) * 8 + (lane & 7);
    const uint32_t aOff = (uint32_t)(swz8(rA, (lane >> 4) & 1) * 2);
    const int cB = wn + ((lane >> 4) & 1) * 8 + (lane & 7);
    const uint32_t bOff = (uint32_t)(swz8(cB, (lane >> 3) & 1) * 2);
    const uint32_t aHiB = (uint32_t)__cvta_generic_to_shared(As_hi) + aOff;
    const uint32_t aLoB = (uint32_t)__cvta_generic_to_shared(As_lo) + aOff;
    const uint32_t bHiB = (uint32_t)__cvta_generic_to_shared(Bs_hi) + bOff;
    const uint32_t bLoB = (uint32_t)__cvta_generic_to_shared(Bs_lo) + bOff;

    float acc[2][4][4];
    #pragma unroll
    for (int i = 0; i < 2; i++)
        #pragma unroll
        for (int j = 0; j < 4; j++)
            #pragma unroll
            for (int q = 0; q < 4; q++) acc[i][j][q] = 0.f;

    const int nit = Ls / 16;   // 128
    // NOTE: non-owning threads (tid>=128) must NOT issue the B copies at all:
    // cp.async with src-size 0 still zero-fills dst, racing the owners' data.
    #define V_ISSUE(s, k0v) {                                               \
        cpa16(aHiS + (uint32_t)(s)*4096, Ah + (k0v), true);                 \
        cpa16(aLoS + (uint32_t)(s)*4096, Al + (k0v), true);                 \
        if (bpred) {                                                        \
            cpa16(bHiS + (uint32_t)(s)*2048, Bh + (k0v), true);             \
            cpa16(bLoS + (uint32_t)(s)*2048, Bl + (k0v), true);             \
        }                                                                   \
        cpa_commit(); }

    #pragma unroll
    for (int s = 0; s < NS-1; s++) if (s < nit) V_ISSUE(s, s*16);

    for (int it = 0; it < nit; it++) {
        cpa_wait<NS-2>();
        __syncthreads();
        const uint32_t stA = (uint32_t)(it & (NS-1)) * 4096;
        const uint32_t stB = (uint32_t)(it & (NS-1)) * 2048;
        uint32_t ah[2][4], al[2][4];
        ldsm4(ah[0], aHiB + stA);  ldsm4(ah[1], aHiB + stA + 512);
        ldsm4(al[0], aLoB + stA);  ldsm4(al[1], aLoB + stA + 512);
        #pragma unroll
        for (int p = 0; p < 2; p++) {
            uint32_t bh2[4], bl2[4];
            ldsm4(bh2, bHiB + stB + p * 512);
            ldsm4(bl2, bLoB + stB + p * 512);
            SPLIT_MMA(acc[0][2*p],   acc[1][2*p],   ah, al, (bh2 + 0), (bl2 + 0));
            SPLIT_MMA(acc[0][2*p+1], acc[1][2*p+1], ah, al, (bh2 + 2), (bl2 + 2));
        }
        int nxt = it + NS - 1;
        if (nxt < nit) { V_ISSUE(nxt & (NS-1), nxt*16); } else { cpa_commit(); }
    }
    #undef V_ISSUE

    #pragma unroll
    for (int mi = 0; mi < 2; mi++) {
        const long long r0 = (long long)b * Ls + i0 + wm + mi * 16 + g;
        #pragma unroll
        for (int nj = 0; nj < 4; nj++) {
            const int c = h * Hd + wn + nj * 8 + tg * 2;
            uint32_t hp, lp;
            bsplit2(acc[mi][nj][0], acc[mi][nj][1], hp, lp);
            *(uint32_t*)&s_ctxh[r0 * Dm + c] = hp;
            *(uint32_t*)&s_ctxl[r0 * Dm + c] = lp;
            bsplit2(acc[mi][nj][2], acc[mi][nj][3], hp, lp);
            *(uint32_t*)&s_ctxh[(r0 + 8) * Dm + c] = hp;
            *(uint32_t*)&s_ctxl[(r0 + 8) * Dm + c] = lp;
        }
    }
}

// ======================== elementwise / small kernels =======================
__global__ void __launch_bounds__(256)
softmax_kernel(float* __restrict__ attn)
{
    const long long row = blockIdx.x;
    float* p = attn + row * (long long)Ls;
    const int tid = threadIdx.x;
    float v[8];
    float mx = -1e30f;
    #pragma unroll
    for (int i = 0; i < 8; i++) { v[i] = p[tid + i*256]; mx = fmaxf(mx, v[i]); }
    mx = blockReduceMax256(mx);
    float s = 0.f;
    #pragma unroll
    for (int i = 0; i < 8; i++) { v[i] = __expf(v[i] - mx); s += v[i]; }
    s = blockReduceSum256(s);
    float inv = 1.f / s;
    #pragma unroll
    for (int i = 0; i < 8; i++) {
        float pv = v[i] * inv;
        long long idx = row * Ls + tid + i*256;
        p[tid + i*256] = pv;
        unsigned short h, l;
        bsplit(pv, h, l);
        s_ph[idx] = h; s_pl[idx] = l;
    }
}

__global__ void __launch_bounds__(256)
add_ln_kernel(const float* __restrict__ a, const float* __restrict__ b,
              const float* __restrict__ gam, const float* __restrict__ bet,
              float* __restrict__ out)
{
    const int t = blockIdx.x, tid = threadIdx.x;
    float v0 = a[(long long)t*Dm + tid]       + b[(long long)t*Dm + tid];
    float v1 = a[(long long)t*Dm + tid + 256] + b[(long long)t*Dm + tid + 256];
    float s = blockReduceSum256(v0 + v1);
    float mean = s * (1.0f / Dm);
    float d0 = v0 - mean, d1 = v1 - mean;
    float sq = blockReduceSum256(d0*d0 + d1*d1);
    float rstd = rsqrtf(sq * (1.0f / Dm) + 1e-5f);
    float o0 = d0 * rstd * gam[tid]       + bet[tid];
    float o1 = d1 * rstd * gam[tid + 256] + bet[tid + 256];
    out[(long long)t*Dm + tid]       = o0;
    out[(long long)t*Dm + tid + 256] = o1;
    unsigned short h, l;
    bsplit(o0, h, l); s_x1h[(long long)t*Dm + tid] = h;       s_x1l[(long long)t*Dm + tid] = l;
    bsplit(o1, h, l); s_x1h[(long long)t*Dm + tid + 256] = h; s_x1l[(long long)t*Dm + tid + 256] = l;
}

__global__ void __launch_bounds__(256)
gate_logits_kernel(const float* __restrict__ gW2, const float* __restrict__ gb2)
{
    const int t = blockIdx.x * 32 + (threadIdx.x >> 3);
    const int e = threadIdx.x & 7;
    const float* row = g_gh + (long long)t * Dm;
    float s = 0.f;
    #pragma unroll 8
    for (int d = 0; d < Dm; d++) s += row[d] * gW2[d*Ee + e];
    g_logits[t*Ee + e] = s + gb2[e];
}

__global__ void init_kernel(float* __restrict__ loss)
{
    if (threadIdx.x < Ee) g_cnt[threadIdx.x] = 0;
    if (threadIdx.x == 0) *loss = 0.0f;
}

__global__ void __launch_bounds__(256)
topk_kernel()
{
    const int t = blockIdx.x * 256 + threadIdx.x;
    if (t >= Tt) return;
    float lg[Ee];
    #pragma unroll
    for (int e = 0; e < Ee; e++) lg[e] = g_logits[t*Ee + e];
    int i1 = 0;
    #pragma unroll
    for (int e = 1; e < Ee; e++) if (lg[e] > lg[i1]) i1 = e;
    int i2 = -1;
    #pragma unroll
    for (int e = 0; e < Ee; e++) if (e != i1 && (i2 < 0 || lg[e] > lg[i2])) i2 = e;
    float mx = lg[i1];
    float s = 0.f;
    #pragma unroll
    for (int e = 0; e < Ee; e++) s += __expf(lg[e] - mx);
    float p1 = __expf(lg[i1] - mx) / s;
    float p2 = __expf(lg[i2] - mx) / s;
    float dn = p1 + p2 + 1e-9f;
    g_wk[2*t + 0] = p1 / dn;
    g_wk[2*t + 1] = p2 / dn;
    int s1 = atomicAdd(&g_cnt[i1], 1); g_list[i1*Tt + s1] = 2*t + 0;
    int s2 = atomicAdd(&g_cnt[i2], 1); g_list[i2*Tt + s2] = 2*t + 1;
}

__global__ void __launch_bounds__(256)
final_ln_kernel(const float* __restrict__ gam, const float* __restrict__ bet,
                float* __restrict__ out)
{
    const int t = blockIdx.x, tid = threadIdx.x;
    const float w0 = g_wk[2*t], w1 = g_wk[2*t + 1];
    float vv[2];
    #pragma unroll
    for (int i = 0; i < 2; i++) {
        int d = tid + i*256;
        float moe = w0 * g_y[(long long)(2*t)   * Dm + d]
                  + w1 * g_y[(long long)(2*t+1) * Dm + d];
        moe = __bfloat162float(__float2bfloat16(moe));
        vv[i] = g_gen[(long long)t*Dm + d] + moe + g_x1[(long long)t*Dm + d];
    }
    float s = blockReduceSum256(vv[0] + vv[1]);
    float mean = s * (1.0f / Dm);
    float d0 = vv[0] - mean, d1 = vv[1] - mean;
    float sq = blockReduceSum256(d0*d0 + d1*d1);
    float rstd = rsqrtf(sq * (1.0f / Dm) + 1e-5f);
    out[(long long)t*Dm + tid]       = d0 * rstd * gam[tid]       + bet[tid];
    out[(long long)t*Dm + tid + 256] = d1 * rstd * gam[tid + 256] + bet[tid + 256];
}

// ------------------------------- launch -------------------------------------
extern "C" void kernel_launch(void* const* d_in, const int* in_sizes, int n_in,
                              void* d_out, int out_size)
{
    const float* x    = (const float*)d_in[0];
    const float* Wq   = (const float*)d_in[1];
    const float* bq   = (const float*)d_in[2];
    const float* Wk   = (const float*)d_in[3];
    const float* bk   = (const float*)d_in[4];
    const float* Wv   = (const float*)d_in[5];
    const float* bv   = (const float*)d_in[6];
    const float* Wo   = (const float*)d_in[7];
    const float* bo   = (const float*)d_in[8];
    const float* ln1g = (const float*)d_in[9];
    const float* ln1b = (const float*)d_in[10];
    const float* gW1  = (const float*)d_in[11];
    const float* gb1  = (const float*)d_in[12];
    const float* gW2  = (const float*)d_in[13];
    const float* gb2  = (const float*)d_in[14];
    const float* eW1  = (const float*)d_in[15];
    const float* eb1  = (const float*)d_in[16];
    const float* eW2  = (const float*)d_in[17];
    const float* eb2  = (const float*)d_in[18];
    const float* geW1 = (const float*)d_in[19];
    const float* geb1 = (const float*)d_in[20];
    const float* geW2 = (const float*)d_in[21];
    const float* geb2 = (const float*)d_in[22];
    const float* ln2g = (const float*)d_in[23];
    const float* ln2b = (const float*)d_in[24];

    float* out  = (float*)d_out;
    float* attn = out + ATTN_OFF;
    float* loss = out + LOSS_OFF;

    float *pv, *ptmp, *px1, *pgh, *pgen;
    cudaGetSymbolAddress((void**)&pv,   g_v);
    cudaGetSymbolAddress((void**)&ptmp, g_tmp);
    cudaGetSymbolAddress((void**)&px1,  g_x1);
    cudaGetSymbolAddress((void**)&pgh,  g_gh);
    cudaGetSymbolAddress((void**)&pgen, g_gen);

    unsigned short *xh,*xl,*qh,*ql,*kh,*kl,*vth,*vtl,*ctxh,*ctxl,*gnh,*gnl;
    unsigned short *wqh,*wql,*wkh,*wkl,*wvh,*wvl,*woh,*wol,*gw1h,*gw1l;
    unsigned short *gew1h,*gew1l,*gew2h,*gew2l,*ew1h,*ew1l,*ew2h,*ew2l;
    cudaGetSymbolAddress((void**)&xh, s_xh);     cudaGetSymbolAddress((void**)&xl, s_xl);
    cudaGetSymbolAddress((void**)&qh, s_qh);     cudaGetSymbolAddress((void**)&ql, s_ql);
    cudaGetSymbolAddress((void**)&kh, s_kh);     cudaGetSymbolAddress((void**)&kl, s_kl);
    cudaGetSymbolAddress((void**)&vth, s_vth);   cudaGetSymbolAddress((void**)&vtl, s_vtl);
    cudaGetSymbolAddress((void**)&ctxh, s_ctxh); cudaGetSymbolAddress((void**)&ctxl, s_ctxl);
    cudaGetSymbolAddress((void**)&gnh, s_gnh);   cudaGetSymbolAddress((void**)&gnl, s_gnl);
    cudaGetSymbolAddress((void**)&wqh, s_wqh);   cudaGetSymbolAddress((void**)&wql, s_wql);
    cudaGetSymbolAddress((void**)&wkh, s_wkh);   cudaGetSymbolAddress((void**)&wkl, s_wkl);
    cudaGetSymbolAddress((void**)&wvh, s_wvh);   cudaGetSymbolAddress((void**)&wvl, s_wvl);
    cudaGetSymbolAddress((void**)&woh, s_woh);   cudaGetSymbolAddress((void**)&wol, s_wol);
    cudaGetSymbolAddress((void**)&gw1h, s_gw1h); cudaGetSymbolAddress((void**)&gw1l, s_gw1l);
    cudaGetSymbolAddress((void**)&gew1h, s_gew1h); cudaGetSymbolAddress((void**)&gew1l, s_gew1l);
    cudaGetSymbolAddress((void**)&gew2h, s_gew2h); cudaGetSymbolAddress((void**)&gew2l, s_gew2l);
    cudaGetSymbolAddress((void**)&ew1h, s_ew1h); cudaGetSymbolAddress((void**)&ew1l, s_ew1l);
    cudaGetSymbolAddress((void**)&ew2h, s_ew2h); cudaGetSymbolAddress((void**)&ew2l, s_ew2l);

    unsigned short *x1h, *x1l, *ehh, *ehl;
    cudaGetSymbolAddress((void**)&x1h, s_x1h);   cudaGetSymbolAddress((void**)&x1l, s_x1l);
    cudaGetSymbolAddress((void**)&ehh, s_ehh);   cudaGetSymbolAddress((void**)&ehl, s_ehl);

    const int SMEM_G = NS * 2048 * 2 * 4;              // 65536 B
    const int SMEM_V = NS * (2048*2 + 1024*2) * 2;     // 49152 B
    static bool attr_done = false;
    if (!attr_done) {
        cudaFuncSetAttribute(gemm_s<0,0>, cudaFuncAttributeMaxDynamicSharedMemorySize, SMEM_G);
        cudaFuncSetAttribute(gemm_s<0,1>, cudaFuncAttributeMaxDynamicSharedMemorySize, SMEM_G);
        cudaFuncSetAttribute(gemm_s<1,0>, cudaFuncAttributeMaxDynamicSharedMemorySize, SMEM_G);
        cudaFuncSetAttribute(gemm_s<1,1>, cudaFuncAttributeMaxDynamicSharedMemorySize, SMEM_G);
        cudaFuncSetAttribute(expert_s<0>, cudaFuncAttributeMaxDynamicSharedMemorySize, SMEM_G);
        cudaFuncSetAttribute(expert_s<1>, cudaFuncAttributeMaxDynamicSharedMemorySize, SMEM_G);
        cudaFuncSetAttribute(scores_s,    cudaFuncAttributeMaxDynamicSharedMemorySize, SMEM_G);
        cudaFuncSetAttribute(attnv_s,     cudaFuncAttributeMaxDynamicSharedMemorySize, SMEM_V);
        attr_done = true;
    }

    dim3 blk(256);

    // -------- operand conversion (once per launch) --------
    esplit_kernel<<<(Tt*Dm + 255)/256, blk>>>(x, xh, xl, Tt*Dm);
    wsplit_t_kernel<<<dim3(Dm/32, Dm/32, 1), blk>>>(Wq, wqh, wql, Dm, Dm);
    wsplit_t_kernel<<<dim3(Dm/32, Dm/32, 1), blk>>>(Wk, wkh, wkl, Dm, Dm);
    wsplit_t_kernel<<<dim3(Dm/32, Dm/32, 1), blk>>>(Wv, wvh, wvl, Dm, Dm);
    wsplit_t_kernel<<<dim3(Dm/32, Dm/32, 1), blk>>>(Wo, woh, wol, Dm, Dm);
    wsplit_t_kernel<<<dim3(Dm/32, Dm/32, 1), blk>>>(gW1, gw1h, gw1l, Dm, Dm);
    wsplit_t_kernel<<<dim3(Fd/32, Dm/32, 1), blk>>>(geW1, gew1h, gew1l, Dm, Fd);
    wsplit_t_kernel<<<dim3(Dm/32, Fd/32, 1), blk>>>(geW2, gew2h, gew2l, Fd, Dm);
    wsplit_t_kernel<<<dim3(Fd/32, Dm/32, Ee), blk>>>(eW1, ew1h, ew1l, Dm, Fd);
    wsplit_t_kernel<<<dim3(Dm/32, Fd/32, Ee), blk>>>(eW2, ew2h, ew2l, Fd, Dm);

    // -------- QKV projections --------
    gemm_s<0,1><<<dim3(Dm/128, Tt/128), blk, SMEM_G>>>(xh, xl, wqh, wql, bq, nullptr, qh, ql, Dm, Dm);
    gemm_s<0,1><<<dim3(Dm/128, Tt/128), blk, SMEM_G>>>(xh, xl, wkh, wkl, bk, nullptr, kh, kl, Dm, Dm);
    gemm_s<0,0><<<dim3(Dm/128, Tt/128), blk, SMEM_G>>>(xh, xl, wvh, wvl, bv, pv, nullptr, nullptr, Dm, Dm);
    // v [T x Dm] -> vT planes [Bb][Dm][Ls]
    wsplit_t_kernel<<<dim3(Dm/32, Ls/32, Bb), blk>>>(pv, vth, vtl, Ls, Dm);

    // -------- attention --------
    scores_s<<<dim3(Ls/128, Ls/128, Bb*Hh), blk, SMEM_G>>>(attn);
    softmax_kernel<<<Bb*Hh*Ls, blk>>>(attn);
    attnv_s<<<dim3(1, Ls/128, Bb*Hh), blk, SMEM_V>>>();
    gemm_s<0,0><<<dim3(Dm/128, Tt/128), blk, SMEM_G>>>(ctxh, ctxl, woh, wol, bo, ptmp, nullptr, nullptr, Dm, Dm);
    add_ln_kernel<<<Tt, blk>>>(x, ptmp, ln1g, ln1b, px1);

    // -------- gate --------
    gemm_s<1,0><<<dim3(Dm/128, Tt/128), blk, SMEM_G>>>(x1h, x1l, gw1h, gw1l, gb1, pgh, nullptr, nullptr, Dm, Dm);
    gate_logits_kernel<<<Tt/32, blk>>>(gW2, gb2);
    init_kernel<<<1, 32>>>(loss);
    topk_kernel<<<Tt/256, blk>>>();

    // -------- routed experts --------
    expert_s<0><<<dim3(Fd/128, Tt/128, Ee), blk, SMEM_G>>>(ew1h, ew1l, eb1);
    expert_s<1><<<dim3(Dm/128, Tt/128, Ee), blk, SMEM_G>>>(ew2h, ew2l, eb2);

    // -------- general expert --------
    gemm_s<1,1><<<dim3(Fd/128, Tt/128), blk, SMEM_G>>>(x1h, x1l, gew1h, gew1l, geb1, nullptr, gnh, gnl, Fd, Dm);
    gemm_s<0,0><<<dim3(Dm/128, Tt/128), blk, SMEM_G>>>(gnh, gnl, gew2h, gew2l, geb2, pgen, nullptr, nullptr, Dm, Fd);

    // -------- combine + LN2 --------
    final_ln_kernel<<<Tt, blk>>>(ln2g, ln2b, out);
}